// round 1
// baseline (speedup 1.0000x reference)
#include <cuda_runtime.h>
#include <cuda_bf16.h>

// ---------------- problem constants ----------------
#define LSEQ   64
#define BATCH  256
#define NIO    4
#define NB     1024      // BATCH*NIO
#define IO_EMB 128
#define XDIM   256       // 2*IO_EMB
#define HID    512       // IO_HID
#define GATE   2048      // 4*HID
#define KCAT   768       // XDIM + HID
#define EH     1024      // ENC_HID
#define VG     4096      // 4*EH
#define TDEC   32
#define NPROD  64

// ---------------- device scratch (static, no allocs) ----------------
__device__ float g_x[LSEQ * NB * XDIM];            // embedded inputs  [L][NB][256]
__device__ float g_Wcat[2 * KCAT * GATE];          // [dir][768][2048] stacked Wi;Wh
__device__ float g_h_enc[2 * NB * HID];            // [dir][NB][512]
__device__ float g_c_enc[2 * NB * HID];
__device__ __nv_bfloat16 g_hs_f[(size_t)LSEQ * NB * HID]; // [L][NB][512]
__device__ __nv_bfloat16 g_hs_b[(size_t)LSEQ * NB * HID];
__device__ float g_gates_enc[2 * NB * GATE];       // per-step gate scratch
__device__ float g_h_dec[BATCH * EH];
__device__ float g_c_dec[BATCH * EH];
__device__ float g_q[BATCH * EH];
__device__ float g_ctx[NB * EH];                   // per-(b,n) attention context
__device__ float g_vXWi[TDEC * VG];                // field_emb @ v_Wi + v_b
__device__ float g_gates_dec[BATCH * VG];
__device__ float g_WcompT[NPROD * 2048];           // transposed W_comp

__device__ __forceinline__ float sigf(float x) { return 1.f / (1.f + expf(-x)); }

// ---------------- setup kernels ----------------
__global__ void k_embed(const int* __restrict__ exs, const int* __restrict__ cls,
                        const float* __restrict__ E) {
    int idx = blockIdx.x * blockDim.x + threadIdx.x;   // L*NB*XDIM
    int j  = idx & (XDIM - 1);
    int tn = idx >> 8;                                 // t*NB + nb
    int tok = (j < IO_EMB) ? exs[tn] : cls[tn];
    int jj  = (j < IO_EMB) ? j : j - IO_EMB;
    g_x[idx] = E[tok * IO_EMB + jj];
}

__global__ void k_wcat(const float* __restrict__ Wi_f, const float* __restrict__ Wh_f,
                       const float* __restrict__ Wi_b, const float* __restrict__ Wh_b) {
    int idx = blockIdx.x * blockDim.x + threadIdx.x;   // 2*KCAT*GATE
    int dir = idx / (KCAT * GATE);
    int r   = idx - dir * (KCAT * GATE);
    int k   = r / GATE;
    int n   = r - k * GATE;
    const float* src;
    int kk;
    if (k < XDIM) { src = dir ? Wi_b : Wi_f; kk = k; }
    else          { src = dir ? Wh_b : Wh_f; kk = k - XDIM; }
    g_Wcat[idx] = src[kk * GATE + n];
}

__global__ void k_setup(const float* __restrict__ W_comp, float* __restrict__ out) {
    int idx = blockIdx.x * blockDim.x + threadIdx.x;   // 2*NB*HID threads
    if (idx < 2 * NB * HID) { g_h_enc[idx] = 0.f; g_c_enc[idx] = 0.f; }
    if (idx < NPROD * 2048) {
        int j = idx / 2048, k = idx - j * 2048;
        g_WcompT[idx] = W_comp[k * NPROD + j];
    }
    if (idx < BATCH) out[idx] = 0.f;
}

// ---------------- generic split-A SGEMM ----------------
// C = A @ B (+ bias row), A columns k<kSplit from A1 (lda1), else A2 (lda2).
// blockIdx.z selects the "a"/"b" pointer set (used for fwd/bwd LSTM directions).
__global__ void __launch_bounds__(256) sgemm(
    const float* __restrict__ A1a, const float* __restrict__ A1b,
    const float* __restrict__ A2a, const float* __restrict__ A2b,
    const float* __restrict__ Ba_, const float* __restrict__ Bb_,
    const float* __restrict__ biasa, const float* __restrict__ biasb,
    float* __restrict__ Ca, float* __restrict__ Cb,
    int M, int N, int K, int kSplit,
    int lda1, int lda2, int ldb, int ldc)
{
    const float* A1 = A1a; const float* A2 = A2a; const float* Bm = Ba_;
    const float* bias = biasa; float* C = Ca;
    if (blockIdx.z == 1) { A1 = A1b; A2 = A2b; Bm = Bb_; bias = biasb; C = Cb; }

    __shared__ float As[16][64];
    __shared__ float Bs[16][64];

    int tid = threadIdx.x;
    int tx = tid & 15, ty = tid >> 4;
    int brow = blockIdx.y * 64;
    int bcol = blockIdx.x * 64;

    float acc[4][4] = {};

    for (int k0 = 0; k0 < K; k0 += 16) {
#pragma unroll
        for (int i = 0; i < 4; i++) {
            int e = tid + i * 256;
            int m = e >> 4, kk = e & 15;
            int gm = brow + m, gk = k0 + kk;
            float v = 0.f;
            if (gm < M && gk < K)
                v = (gk < kSplit) ? A1[(size_t)gm * lda1 + gk]
                                  : A2[(size_t)gm * lda2 + (gk - kSplit)];
            As[kk][m] = v;
        }
#pragma unroll
        for (int i = 0; i < 4; i++) {
            int e = tid + i * 256;
            int kk = e >> 6, n = e & 63;
            int gk = k0 + kk, gn = bcol + n;
            Bs[kk][n] = (gk < K && gn < N) ? Bm[(size_t)gk * ldb + gn] : 0.f;
        }
        __syncthreads();
#pragma unroll
        for (int kk = 0; kk < 16; kk++) {
            float4 a4 = *(const float4*)&As[kk][ty * 4];
            float4 b4 = *(const float4*)&Bs[kk][tx * 4];
            float a[4] = {a4.x, a4.y, a4.z, a4.w};
            float bb[4] = {b4.x, b4.y, b4.z, b4.w};
#pragma unroll
            for (int im = 0; im < 4; im++)
#pragma unroll
                for (int in = 0; in < 4; in++)
                    acc[im][in] += a[im] * bb[in];
        }
        __syncthreads();
    }

#pragma unroll
    for (int im = 0; im < 4; im++) {
        int row = brow + ty * 4 + im;
        if (row >= M) continue;
#pragma unroll
        for (int in = 0; in < 4; in++) {
            int col = bcol + tx * 4 + in;
            if (col >= N) continue;
            float v = acc[im][in];
            if (bias) v += bias[col];
            C[(size_t)row * ldc + col] = v;
        }
    }
}

// ---------------- encoder pointwise LSTM update ----------------
__global__ void k_enc_point(const float* __restrict__ b_f, const float* __restrict__ b_b, int s) {
    int idx = blockIdx.x * blockDim.x + threadIdx.x;   // 2*NB*HID
    int dir = idx >> 19;                               // NB*HID = 2^19
    int r   = idx & ((1 << 19) - 1);
    int nb  = r >> 9;
    int u   = r & 511;
    const float* gates = g_gates_enc + (size_t)dir * NB * GATE + (size_t)nb * GATE;
    const float* bias  = dir ? b_b : b_f;
    float gi = gates[u]            + bias[u];
    float gf = gates[512 + u]      + bias[512 + u];
    float gg = gates[1024 + u]     + bias[1024 + u];
    float go = gates[1536 + u]     + bias[1536 + u];
    float c = g_c_enc[idx];
    c = sigf(gf) * c + sigf(gi) * tanhf(gg);
    float h = sigf(go) * tanhf(c);
    g_c_enc[idx] = c;
    g_h_enc[idx] = h;
    int t = dir ? (LSEQ - 1 - s) : s;
    __nv_bfloat16* dst = dir ? g_hs_b : g_hs_f;
    dst[(size_t)t * NB * HID + r] = __float2bfloat16(h);
}

// ---------------- pool final encoder states -> decoder init ----------------
__global__ void k_pool() {
    int idx = blockIdx.x * blockDim.x + threadIdx.x;   // BATCH*EH
    int b = idx >> 10;
    int e = idx & 1023;
    int base = (e < 512) ? 0 : NB * HID;
    int ee   = (e < 512) ? e : e - 512;
    float hm = -1e30f, cm = -1e30f;
#pragma unroll
    for (int n = 0; n < 4; n++) {
        int off = base + (b * 4 + n) * HID + ee;
        hm = fmaxf(hm, g_h_enc[off]);
        cm = fmaxf(cm, g_c_enc[off]);
    }
    g_h_dec[idx] = hm;
    g_c_dec[idx] = cm;
}

// ---------------- attention: online softmax, one pass over hs ----------------
__global__ void __launch_bounds__(256) k_attn() {
    int nb = blockIdx.x;         // b*4 + n
    int b  = nb >> 2;
    int tid = threadIdx.x;
    int lane = tid & 31, warp = tid >> 5;

    __shared__ float red[8];
    __shared__ float sc_sh;

    const float* q = g_q + (size_t)b * EH;
    float q0 = q[tid], q1 = q[tid + 256], q2 = q[tid + 512], q3 = q[tid + 768];

    float m = -1e30f, s = 0.f;
    float a0 = 0.f, a1 = 0.f, a2 = 0.f, a3 = 0.f;

    for (int l = 0; l < LSEQ; l++) {
        const __nv_bfloat16* pf = g_hs_f + ((size_t)l * NB + nb) * HID;
        const __nv_bfloat16* pb = g_hs_b + ((size_t)l * NB + nb) * HID;
        float v0 = __bfloat162float(pf[tid]);
        float v1 = __bfloat162float(pf[tid + 256]);
        float v2 = __bfloat162float(pb[tid]);
        float v3 = __bfloat162float(pb[tid + 256]);
        float p = v0 * q0 + v1 * q1 + v2 * q2 + v3 * q3;
#pragma unroll
        for (int off = 16; off > 0; off >>= 1)
            p += __shfl_down_sync(0xffffffffu, p, off);
        if (lane == 0) red[warp] = p;
        __syncthreads();
        if (tid == 0) {
            float t = 0.f;
#pragma unroll
            for (int w = 0; w < 8; w++) t += red[w];
            sc_sh = t;
        }
        __syncthreads();
        float score = sc_sh;
        float mn = fmaxf(m, score);
        float scale = __expf(m - mn);
        float p2 = __expf(score - mn);
        s = s * scale + p2;
        a0 = a0 * scale + p2 * v0;
        a1 = a1 * scale + p2 * v1;
        a2 = a2 * scale + p2 * v2;
        a3 = a3 * scale + p2 * v3;
        m = mn;
    }
    float inv = 1.f / s;
    float* ctx = g_ctx + (size_t)nb * EH;
    ctx[tid]       = a0 * inv;
    ctx[tid + 256] = a1 * inv;
    ctx[tid + 512] = a2 * inv;
    ctx[tid + 768] = a3 * inv;
}

// ---------------- classifier: pooled ctx, logits, logsumexp, NLL ----------------
__global__ void __launch_bounds__(256) k_cls(const float* __restrict__ b_comp,
                                             const int* __restrict__ actions,
                                             float* __restrict__ out, int t) {
    int b = blockIdx.x;
    int tid = threadIdx.x;
    int lane = tid & 31, warp = tid >> 5;
    __shared__ float feat[2048];
    __shared__ float lg[NPROD];

    for (int e = tid; e < 2048; e += 256) {
        float v;
        if (e < 1024) {
            v = g_h_dec[(size_t)b * EH + e];
        } else {
            int ee = e - 1024;
            float m0 = g_ctx[(size_t)(b * 4 + 0) * EH + ee];
            float m1 = g_ctx[(size_t)(b * 4 + 1) * EH + ee];
            float m2 = g_ctx[(size_t)(b * 4 + 2) * EH + ee];
            float m3 = g_ctx[(size_t)(b * 4 + 3) * EH + ee];
            v = fmaxf(fmaxf(m0, m1), fmaxf(m2, m3));
        }
        feat[e] = v;
    }
    __syncthreads();

    for (int j = warp; j < NPROD; j += 8) {
        const float* w = g_WcompT + (size_t)j * 2048;
        float p = 0.f;
        for (int k = lane; k < 2048; k += 32)
            p += feat[k] * w[k];
#pragma unroll
        for (int off = 16; off > 0; off >>= 1)
            p += __shfl_down_sync(0xffffffffu, p, off);
        if (lane == 0) lg[j] = p + b_comp[j];
    }
    __syncthreads();
    if (tid == 0) {
        float mx = -1e30f;
        for (int j = 0; j < NPROD; j++) mx = fmaxf(mx, lg[j]);
        float sum = 0.f;
        for (int j = 0; j < NPROD; j++) sum += __expf(lg[j] - mx);
        float lse = mx + __logf(sum);
        int a = actions[b * TDEC + t];
        out[b] += lse - lg[a];
    }
}

// ---------------- decoder pointwise LSTM update ----------------
__global__ void k_dec_point() {
    int idx = blockIdx.x * blockDim.x + threadIdx.x;   // BATCH*EH
    int b = idx >> 10;
    int u = idx & 1023;
    const float* g = g_gates_dec + (size_t)b * VG;
    float gi = g[u];
    float gf = g[EH + u];
    float gg = g[2 * EH + u];
    float go = g[3 * EH + u];
    float c = g_c_dec[idx];
    c = sigf(gf) * c + sigf(gi) * tanhf(gg);
    float h = sigf(go) * tanhf(c);
    g_c_dec[idx] = c;
    g_h_dec[idx] = h;
}

// ---------------- host orchestration ----------------
extern "C" void kernel_launch(void* const* d_in, const int* in_sizes, int n_in,
                              void* d_out, int out_size) {
    const int*   exs     = (const int*)  d_in[0];
    const int*   cls     = (const int*)  d_in[1];
    const float* E       = (const float*)d_in[2];
    const float* Wi_f    = (const float*)d_in[3];
    const float* Wh_f    = (const float*)d_in[4];
    const float* b_f     = (const float*)d_in[5];
    const float* Wi_b    = (const float*)d_in[6];
    const float* Wh_b    = (const float*)d_in[7];
    const float* b_b     = (const float*)d_in[8];
    const float* W_attn  = (const float*)d_in[9];
    const float* W_comp  = (const float*)d_in[10];
    const float* b_comp  = (const float*)d_in[11];
    const float* v_Wi    = (const float*)d_in[12];
    const float* v_Wh    = (const float*)d_in[13];
    const float* v_b     = (const float*)d_in[14];
    const float* field   = (const float*)d_in[15];
    const int*   actions = (const int*)  d_in[16];
    float* out = (float*)d_out;

    float *p_x, *p_wcat, *p_h_enc, *p_gates_enc, *p_h_dec, *p_q, *p_vXWi, *p_gates_dec;
    cudaGetSymbolAddress((void**)&p_x, g_x);
    cudaGetSymbolAddress((void**)&p_wcat, g_Wcat);
    cudaGetSymbolAddress((void**)&p_h_enc, g_h_enc);
    cudaGetSymbolAddress((void**)&p_gates_enc, g_gates_enc);
    cudaGetSymbolAddress((void**)&p_h_dec, g_h_dec);
    cudaGetSymbolAddress((void**)&p_q, g_q);
    cudaGetSymbolAddress((void**)&p_vXWi, g_vXWi);
    cudaGetSymbolAddress((void**)&p_gates_dec, g_gates_dec);

    // ---- setup ----
    k_embed<<<(LSEQ * NB * XDIM) / 256, 256>>>(exs, cls, E);
    k_wcat<<<(2 * KCAT * GATE) / 256, 256>>>(Wi_f, Wh_f, Wi_b, Wh_b);
    k_setup<<<(2 * NB * HID) / 256, 256>>>(W_comp, out);

    // vXWi = field_emb @ v_Wi + v_b   [32, 4096]
    sgemm<<<dim3(VG / 64, 1, 1), 256>>>(
        field, nullptr, nullptr, nullptr, v_Wi, nullptr, v_b, nullptr,
        p_vXWi, nullptr, TDEC, VG, EH, EH, EH, 0, VG, VG);

    // ---- biLSTM encoder: 64 steps, fwd (z=0) + bwd (z=1) ----
    for (int s = 0; s < LSEQ; s++) {
        sgemm<<<dim3(GATE / 64, NB / 64, 2), 256>>>(
            p_x + (size_t)s * NB * XDIM,
            p_x + (size_t)(LSEQ - 1 - s) * NB * XDIM,
            p_h_enc, p_h_enc + NB * HID,
            p_wcat, p_wcat + KCAT * GATE,
            nullptr, nullptr,
            p_gates_enc, p_gates_enc + NB * GATE,
            NB, GATE, KCAT, XDIM, XDIM, HID, GATE, GATE);
        k_enc_point<<<(2 * NB * HID) / 256, 256>>>(b_f, b_b, s);
    }

    // ---- decoder init: max-pool final states over IO examples ----
    k_pool<<<(BATCH * EH) / 256, 256>>>();

    // ---- decoder: 32 steps ----
    for (int t = 0; t < TDEC; t++) {
        // q = h @ W_attn
        sgemm<<<dim3(EH / 64, BATCH / 64, 1), 256>>>(
            p_h_dec, nullptr, nullptr, nullptr, W_attn, nullptr, nullptr, nullptr,
            p_q, nullptr, BATCH, EH, EH, EH, EH, 0, EH, EH);
        // attention over io context vectors
        k_attn<<<NB, 256>>>();
        // classifier NLL accumulation
        k_cls<<<BATCH, 256>>>(b_comp, actions, out, t);
        // v-lstm gates = vXWi[t] + h @ v_Wh
        sgemm<<<dim3(VG / 64, BATCH / 64, 1), 256>>>(
            p_h_dec, nullptr, nullptr, nullptr, v_Wh, nullptr,
            p_vXWi + (size_t)t * VG, nullptr,
            p_gates_dec, nullptr, BATCH, VG, EH, EH, EH, 0, VG, VG);
        k_dec_point<<<(BATCH * EH) / 256, 256>>>();
    }
}

// round 3
// speedup vs baseline: 4.5543x; 4.5543x over previous
#include <cuda_runtime.h>
#include <cuda_bf16.h>
#include <mma.h>
#include <cstdint>
#include <cstddef>
using namespace nvcuda;

// ---------------- problem constants ----------------
#define LSEQ   64
#define BATCH  256
#define NIO    4
#define NB     1024      // BATCH*NIO
#define IO_EMB 128
#define XDIM   256       // 2*IO_EMB
#define HID    512       // IO_HID
#define GATE   2048      // 4*HID
#define KCAT   768       // XDIM + HID
#define EH     1024      // ENC_HID
#define VG     4096      // 4*EH
#define TDEC   32
#define NPROD  64

// ---------------- device scratch (static, no allocs) ----------------
__device__ __nv_bfloat16 g_x[(size_t)LSEQ * NB * XDIM];      // embedded inputs (bf16)
__device__ __nv_bfloat16 g_cat[2 * NB * KCAT];               // [dir][NB][768] = [x_t | h]
__device__ __nv_bfloat16 g_Wcat[2 * KCAT * GATE];            // [dir][768][2048] stacked Wi;Wh
__device__ float g_h_enc[2 * NB * HID];
__device__ float g_c_enc[2 * NB * HID];
__device__ __nv_bfloat16 g_hs_f[(size_t)LSEQ * NB * HID];
__device__ __nv_bfloat16 g_hs_b[(size_t)LSEQ * NB * HID];
__device__ float g_gates_enc[2 * NB * GATE];
__device__ float g_h_dec[BATCH * EH];
__device__ float g_c_dec[BATCH * EH];
__device__ __nv_bfloat16 g_hdec_bf[BATCH * EH];
__device__ float g_q[BATCH * EH];
__device__ float g_ctx[NB * EH];
__device__ float g_vXWi[TDEC * VG];
__device__ float g_gates_dec[BATCH * VG];
__device__ float g_WcompT[NPROD * 2048];
__device__ __nv_bfloat16 g_Wattn_bf[EH * 2 * HID];
__device__ __nv_bfloat16 g_vWi_bf[EH * VG];
__device__ __nv_bfloat16 g_vWh_bf[EH * VG];
__device__ __nv_bfloat16 g_field_bf[TDEC * EH];

__device__ __forceinline__ float sigf(float x) { return 1.f / (1.f + expf(-x)); }

// ---------------- cp.async helpers ----------------
__device__ __forceinline__ void cp16(void* dst, const void* src, bool valid) {
    unsigned int d = (unsigned int)__cvta_generic_to_shared(dst);
    int sz = valid ? 16 : 0;
    asm volatile("cp.async.cg.shared.global [%0], [%1], 16, %2;" :: "r"(d), "l"(src), "r"(sz));
}
__device__ __forceinline__ void cp_commit() { asm volatile("cp.async.commit_group;"); }
__device__ __forceinline__ void cp_wait1()  { asm volatile("cp.async.wait_group 1;"); }
__device__ __forceinline__ void cp_wait0()  { asm volatile("cp.async.wait_group 0;"); }

// ---------------- bf16 tensor-core GEMM ----------------
// C[M,N] = A[M,K] @ B[K,N], fp32 accumulate. blockIdx.z picks pointer set.
// Requirements: K % 32 == 0, N % 128 == 0, M % 16 == 0 (store guard at frag level).
#define BM 128
#define BN 128
#define BK 32

__global__ void __launch_bounds__(256) gemm_bf16(
    const __nv_bfloat16* __restrict__ Aa, const __nv_bfloat16* __restrict__ Ab,
    const __nv_bfloat16* __restrict__ Ba, const __nv_bfloat16* __restrict__ Bb,
    float* __restrict__ Ca, float* __restrict__ Cb,
    int M, int N, int K, int lda, int ldb, int ldc)
{
    const __nv_bfloat16* A = blockIdx.z ? Ab : Aa;
    const __nv_bfloat16* B = blockIdx.z ? Bb : Ba;
    float* C = blockIdx.z ? Cb : Ca;

    __shared__ __nv_bfloat16 As[2][BM][40];   // padded stride 40
    __shared__ __nv_bfloat16 Bs[2][BK][136];  // padded stride 136

    int tid  = threadIdx.x;
    int warp = tid >> 5;
    int wr = warp >> 1, wc = warp & 1;        // 4x2 warp grid
    int brow = blockIdx.y * BM, bcol = blockIdx.x * BN;
    int m0 = wr * 32, n0 = wc * 64;

    wmma::fragment<wmma::accumulator, 16, 16, 16, float> acc[2][4];
#pragma unroll
    for (int i = 0; i < 2; i++)
#pragma unroll
        for (int j = 0; j < 4; j++)
            wmma::fill_fragment(acc[i][j], 0.f);

    int nk = K / BK;

    // tile loader
    auto load_tile = [&](int buf, int k0) {
#pragma unroll
        for (int i = 0; i < 2; i++) {
            int cid = tid + i * 256;          // 0..511 : A chunks
            int row = cid >> 2;
            int col = (cid & 3) * 8;
            const __nv_bfloat16* src = A + (size_t)(brow + row) * lda + k0 + col;
            bool v = (brow + row) < M;
            cp16(&As[buf][row][col], v ? (const void*)src : (const void*)A, v);
        }
#pragma unroll
        for (int i = 0; i < 2; i++) {
            int cid = tid + i * 256;          // 0..511 : B chunks
            int row = cid >> 4;
            int col = (cid & 15) * 8;
            const __nv_bfloat16* src = B + (size_t)(k0 + row) * ldb + bcol + col;
            cp16(&Bs[buf][row][col], src, true);
        }
    };

    load_tile(0, 0);
    cp_commit();

    int buf = 0;
    for (int kt = 0; kt < nk; kt++) {
        if (kt + 1 < nk) {
            load_tile(buf ^ 1, (kt + 1) * BK);
            cp_commit();
            cp_wait1();
        } else {
            cp_wait0();
        }
        __syncthreads();

#pragma unroll
        for (int kk = 0; kk < BK; kk += 16) {
            wmma::fragment<wmma::matrix_a, 16, 16, 16, __nv_bfloat16, wmma::row_major> af[2];
            wmma::fragment<wmma::matrix_b, 16, 16, 16, __nv_bfloat16, wmma::row_major> bfr[4];
#pragma unroll
            for (int i = 0; i < 2; i++)
                wmma::load_matrix_sync(af[i], &As[buf][m0 + i * 16][kk], 40);
#pragma unroll
            for (int j = 0; j < 4; j++)
                wmma::load_matrix_sync(bfr[j], &Bs[buf][kk][n0 + j * 16], 136);
#pragma unroll
            for (int i = 0; i < 2; i++)
#pragma unroll
                for (int j = 0; j < 4; j++)
                    wmma::mma_sync(acc[i][j], af[i], bfr[j], acc[i][j]);
        }
        __syncthreads();
        buf ^= 1;
    }

#pragma unroll
    for (int i = 0; i < 2; i++) {
        int gm = brow + m0 + i * 16;
        if (gm >= M) continue;
#pragma unroll
        for (int j = 0; j < 4; j++)
            wmma::store_matrix_sync(&C[(size_t)gm * ldc + bcol + n0 + j * 16],
                                    acc[i][j], ldc, wmma::mem_row_major);
    }
}

// ---------------- setup kernels ----------------
__global__ void k_embed(const int* __restrict__ exs, const int* __restrict__ cls,
                        const float* __restrict__ E) {
    int idx = blockIdx.x * blockDim.x + threadIdx.x;   // L*NB*XDIM
    int j  = idx & (XDIM - 1);
    int tn = idx >> 8;
    int tok = (j < IO_EMB) ? exs[tn] : cls[tn];
    int jj  = (j < IO_EMB) ? j : j - IO_EMB;
    g_x[idx] = __float2bfloat16(E[tok * IO_EMB + jj]);
}

__global__ void k_wcat(const float* __restrict__ Wi_f, const float* __restrict__ Wh_f,
                       const float* __restrict__ Wi_b, const float* __restrict__ Wh_b) {
    int idx = blockIdx.x * blockDim.x + threadIdx.x;   // 2*KCAT*GATE
    int dir = idx / (KCAT * GATE);
    int r   = idx - dir * (KCAT * GATE);
    int k   = r / GATE;
    int n   = r - k * GATE;
    const float* src;
    int kk;
    if (k < XDIM) { src = dir ? Wi_b : Wi_f; kk = k; }
    else          { src = dir ? Wh_b : Wh_f; kk = k - XDIM; }
    g_Wcat[idx] = __float2bfloat16(src[kk * GATE + n]);
}

__global__ void k_conv(const float* __restrict__ W_attn, const float* __restrict__ v_Wi,
                       const float* __restrict__ v_Wh, const float* __restrict__ field,
                       const float* __restrict__ W_comp, float* __restrict__ out) {
    int idx = blockIdx.x * blockDim.x + threadIdx.x;   // EH*VG threads
    if (idx < EH * VG) {
        g_vWi_bf[idx] = __float2bfloat16(v_Wi[idx]);
        g_vWh_bf[idx] = __float2bfloat16(v_Wh[idx]);
    }
    if (idx < EH * 2 * HID) g_Wattn_bf[idx] = __float2bfloat16(W_attn[idx]);
    if (idx < TDEC * EH)    g_field_bf[idx] = __float2bfloat16(field[idx]);
    if (idx < NPROD * 2048) {
        int j = idx / 2048, k = idx - j * 2048;
        g_WcompT[idx] = W_comp[k * NPROD + j];
    }
    if (idx < BATCH) out[idx] = 0.f;
}

__global__ void k_init() {
    int idx = blockIdx.x * blockDim.x + threadIdx.x;   // 2*NB*KCAT
    int dir = idx / (NB * KCAT);
    int r   = idx - dir * (NB * KCAT);
    int nb  = r / KCAT;
    int col = r - nb * KCAT;
    if (col < XDIM) {
        int t0 = dir ? (LSEQ - 1) : 0;
        g_cat[idx] = g_x[((size_t)t0 * NB + nb) * XDIM + col];
    } else {
        g_cat[idx] = __float2bfloat16(0.f);
    }
    if (idx < 2 * NB * HID) g_c_enc[idx] = 0.f;
}

// ---------------- encoder pointwise LSTM update ----------------
__global__ void k_enc_point(const float* __restrict__ b_f, const float* __restrict__ b_b, int s) {
    int idx = blockIdx.x * blockDim.x + threadIdx.x;   // 2*NB*HID
    int dir = idx >> 19;
    int r   = idx & ((1 << 19) - 1);
    int nb  = r >> 9;
    int u   = r & 511;
    const float* gates = g_gates_enc + (size_t)dir * NB * GATE + (size_t)nb * GATE;
    const float* bias  = dir ? b_b : b_f;
    float gi = gates[u]        + bias[u];
    float gf = gates[512 + u]  + bias[512 + u];
    float gg = gates[1024 + u] + bias[1024 + u];
    float go = gates[1536 + u] + bias[1536 + u];
    float c = g_c_enc[idx];
    c = sigf(gf) * c + sigf(gi) * tanhf(gg);
    float h = sigf(go) * tanhf(c);
    g_c_enc[idx] = c;
    g_h_enc[idx] = h;
    int t = dir ? (LSEQ - 1 - s) : s;
    __nv_bfloat16* dst = dir ? g_hs_b : g_hs_f;
    __nv_bfloat16 hb = __float2bfloat16(h);
    dst[(size_t)t * NB * HID + r] = hb;
    // refresh concat buffer for next step
    __nv_bfloat16* cat = g_cat + ((size_t)dir * NB + nb) * KCAT;
    cat[XDIM + u] = hb;
    if (u < XDIM) {
        int tn = dir ? (LSEQ - 2 - s) : (s + 1);
        if (tn >= 0 && tn < LSEQ)
            cat[u] = g_x[((size_t)tn * NB + nb) * XDIM + u];
    }
}

// ---------------- pool final encoder states -> decoder init ----------------
__global__ void k_pool() {
    int idx = blockIdx.x * blockDim.x + threadIdx.x;   // BATCH*EH
    int b = idx >> 10;
    int e = idx & 1023;
    int base = (e < 512) ? 0 : NB * HID;
    int ee   = (e < 512) ? e : e - 512;
    float hm = -1e30f, cm = -1e30f;
#pragma unroll
    for (int n = 0; n < 4; n++) {
        int off = base + (b * 4 + n) * HID + ee;
        hm = fmaxf(hm, g_h_enc[off]);
        cm = fmaxf(cm, g_c_enc[off]);
    }
    g_h_dec[idx] = hm;
    g_c_dec[idx] = cm;
    g_hdec_bf[idx] = __float2bfloat16(hm);
}

// ---------------- attention: online softmax, one pass, vectorized ----------------
__global__ void __launch_bounds__(128) k_attn() {
    int nb = blockIdx.x;
    int b  = nb >> 2;
    int tid = threadIdx.x;
    int lane = tid & 31, warp = tid >> 5;

    __shared__ float red[2][4];

    const float* q = g_q + (size_t)b * EH;
    float qf[4], qb[4];
#pragma unroll
    for (int i = 0; i < 4; i++) { qf[i] = q[tid * 4 + i]; qb[i] = q[512 + tid * 4 + i]; }

    float m = -1e30f, s = 0.f;
    float af[4] = {0.f, 0.f, 0.f, 0.f};
    float ab[4] = {0.f, 0.f, 0.f, 0.f};

    for (int l = 0; l < LSEQ; l++) {
        const uint2* pf = (const uint2*)(g_hs_f + ((size_t)l * NB + nb) * HID) + tid;
        const uint2* pb = (const uint2*)(g_hs_b + ((size_t)l * NB + nb) * HID) + tid;
        uint2 df = *pf, db = *pb;
        float vf[4], vb[4];
        {
            float2 t0 = __bfloat1622float2(*reinterpret_cast<__nv_bfloat162*>(&df.x));
            float2 t1 = __bfloat1622float2(*reinterpret_cast<__nv_bfloat162*>(&df.y));
            vf[0] = t0.x; vf[1] = t0.y; vf[2] = t1.x; vf[3] = t1.y;
            float2 u0 = __bfloat1622float2(*reinterpret_cast<__nv_bfloat162*>(&db.x));
            float2 u1 = __bfloat1622float2(*reinterpret_cast<__nv_bfloat162*>(&db.y));
            vb[0] = u0.x; vb[1] = u0.y; vb[2] = u1.x; vb[3] = u1.y;
        }
        float p = 0.f;
#pragma unroll
        for (int i = 0; i < 4; i++) p += vf[i] * qf[i] + vb[i] * qb[i];
#pragma unroll
        for (int off = 16; off > 0; off >>= 1)
            p += __shfl_down_sync(0xffffffffu, p, off);
        if (lane == 0) red[l & 1][warp] = p;
        __syncthreads();
        float score = red[l & 1][0] + red[l & 1][1] + red[l & 1][2] + red[l & 1][3];

        float mn = fmaxf(m, score);
        float scale = __expf(m - mn);
        float p2 = __expf(score - mn);
        s = s * scale + p2;
#pragma unroll
        for (int i = 0; i < 4; i++) {
            af[i] = af[i] * scale + p2 * vf[i];
            ab[i] = ab[i] * scale + p2 * vb[i];
        }
        m = mn;
    }
    float inv = 1.f / s;
    float* ctx = g_ctx + (size_t)nb * EH;
#pragma unroll
    for (int i = 0; i < 4; i++) {
        ctx[tid * 4 + i]       = af[i] * inv;
        ctx[512 + tid * 4 + i] = ab[i] * inv;
    }
}

// ---------------- classifier: pooled ctx, logits, logsumexp, NLL ----------------
__global__ void __launch_bounds__(256) k_cls(const float* __restrict__ b_comp,
                                             const int* __restrict__ actions,
                                             float* __restrict__ out, int t) {
    int b = blockIdx.x;
    int tid = threadIdx.x;
    int lane = tid & 31, warp = tid >> 5;
    __shared__ float feat[2048];
    __shared__ float lg[NPROD];

    for (int e = tid; e < 2048; e += 256) {
        float v;
        if (e < 1024) {
            v = g_h_dec[(size_t)b * EH + e];
        } else {
            int ee = e - 1024;
            float m0 = g_ctx[(size_t)(b * 4 + 0) * EH + ee];
            float m1 = g_ctx[(size_t)(b * 4 + 1) * EH + ee];
            float m2 = g_ctx[(size_t)(b * 4 + 2) * EH + ee];
            float m3 = g_ctx[(size_t)(b * 4 + 3) * EH + ee];
            v = fmaxf(fmaxf(m0, m1), fmaxf(m2, m3));
        }
        feat[e] = v;
    }
    __syncthreads();

    for (int j = warp; j < NPROD; j += 8) {
        const float* w = g_WcompT + (size_t)j * 2048;
        float p = 0.f;
        for (int k = lane; k < 2048; k += 32)
            p += feat[k] * w[k];
#pragma unroll
        for (int off = 16; off > 0; off >>= 1)
            p += __shfl_down_sync(0xffffffffu, p, off);
        if (lane == 0) lg[j] = p + b_comp[j];
    }
    __syncthreads();
    if (tid == 0) {
        float mx = -1e30f;
        for (int j = 0; j < NPROD; j++) mx = fmaxf(mx, lg[j]);
        float sum = 0.f;
        for (int j = 0; j < NPROD; j++) sum += __expf(lg[j] - mx);
        float lse = mx + __logf(sum);
        int a = actions[b * TDEC + t];
        out[b] += lse - lg[a];
    }
}

// ---------------- decoder pointwise LSTM update ----------------
__global__ void k_dec_point(const float* __restrict__ v_b, int t) {
    int idx = blockIdx.x * blockDim.x + threadIdx.x;   // BATCH*EH
    int b = idx >> 10;
    int u = idx & 1023;
    const float* g  = g_gates_dec + (size_t)b * VG;
    const float* xg = g_vXWi + (size_t)t * VG;
    float gi = g[u]          + xg[u]          + v_b[u];
    float gf = g[EH + u]     + xg[EH + u]     + v_b[EH + u];
    float gg = g[2 * EH + u] + xg[2 * EH + u] + v_b[2 * EH + u];
    float go = g[3 * EH + u] + xg[3 * EH + u] + v_b[3 * EH + u];
    float c = g_c_dec[idx];
    c = sigf(gf) * c + sigf(gi) * tanhf(gg);
    float h = sigf(go) * tanhf(c);
    g_c_dec[idx] = c;
    g_h_dec[idx] = h;
    g_hdec_bf[idx] = __float2bfloat16(h);
}

// ---------------- host orchestration ----------------
extern "C" void kernel_launch(void* const* d_in, const int* in_sizes, int n_in,
                              void* d_out, int out_size) {
    const int*   exs     = (const int*)  d_in[0];
    const int*   cls     = (const int*)  d_in[1];
    const float* E       = (const float*)d_in[2];
    const float* Wi_f    = (const float*)d_in[3];
    const float* Wh_f    = (const float*)d_in[4];
    const float* b_f     = (const float*)d_in[5];
    const float* Wi_b    = (const float*)d_in[6];
    const float* Wh_b    = (const float*)d_in[7];
    const float* b_b     = (const float*)d_in[8];
    const float* W_attn  = (const float*)d_in[9];
    const float* W_comp  = (const float*)d_in[10];
    const float* b_comp  = (const float*)d_in[11];
    const float* v_Wi    = (const float*)d_in[12];
    const float* v_Wh    = (const float*)d_in[13];
    const float* v_b     = (const float*)d_in[14];
    const float* field   = (const float*)d_in[15];
    const int*   actions = (const int*)  d_in[16];
    float* out = (float*)d_out;

    __nv_bfloat16 *p_cat, *p_wcat, *p_hdec_bf, *p_Wattn_bf, *p_vWi_bf, *p_vWh_bf, *p_field_bf;
    float *p_gates_enc, *p_q, *p_vXWi, *p_gates_dec;
    cudaGetSymbolAddress((void**)&p_cat, g_cat);
    cudaGetSymbolAddress((void**)&p_wcat, g_Wcat);
    cudaGetSymbolAddress((void**)&p_hdec_bf, g_hdec_bf);
    cudaGetSymbolAddress((void**)&p_Wattn_bf, g_Wattn_bf);
    cudaGetSymbolAddress((void**)&p_vWi_bf, g_vWi_bf);
    cudaGetSymbolAddress((void**)&p_vWh_bf, g_vWh_bf);
    cudaGetSymbolAddress((void**)&p_field_bf, g_field_bf);
    cudaGetSymbolAddress((void**)&p_gates_enc, g_gates_enc);
    cudaGetSymbolAddress((void**)&p_q, g_q);
    cudaGetSymbolAddress((void**)&p_vXWi, g_vXWi);
    cudaGetSymbolAddress((void**)&p_gates_dec, g_gates_dec);

    // ---- setup ----
    k_embed<<<(LSEQ * NB * XDIM) / 256, 256>>>(exs, cls, E);
    k_wcat<<<(2 * KCAT * GATE) / 256, 256>>>(Wi_f, Wh_f, Wi_b, Wh_b);
    k_conv<<<(EH * VG) / 256, 256>>>(W_attn, v_Wi, v_Wh, field, W_comp, out);
    k_init<<<(2 * NB * KCAT) / 256, 256>>>();

    // vXWi = field_emb @ v_Wi   [32, 4096]  (v_b added in k_dec_point)
    gemm_bf16<<<dim3(VG / BN, 1, 1), 256>>>(
        p_field_bf, nullptr, p_vWi_bf, nullptr, p_vXWi, nullptr,
        TDEC, VG, EH, EH, VG, VG);

    // ---- biLSTM encoder: 64 steps, fwd (z=0) + bwd (z=1) ----
    for (int s = 0; s < LSEQ; s++) {
        gemm_bf16<<<dim3(GATE / BN, NB / BM, 2), 256>>>(
            p_cat, p_cat + (size_t)NB * KCAT,
            p_wcat, p_wcat + (size_t)KCAT * GATE,
            p_gates_enc, p_gates_enc + (size_t)NB * GATE,
            NB, GATE, KCAT, KCAT, GATE, GATE);
        k_enc_point<<<(2 * NB * HID) / 256, 256>>>(b_f, b_b, s);
    }

    // ---- decoder init ----
    k_pool<<<(BATCH * EH) / 256, 256>>>();

    // ---- decoder: 32 steps ----
    for (int t = 0; t < TDEC; t++) {
        // q = h @ W_attn
        gemm_bf16<<<dim3(EH / BN, BATCH / BM, 1), 256>>>(
            p_hdec_bf, nullptr, p_Wattn_bf, nullptr, p_q, nullptr,
            BATCH, EH, EH, EH, EH, EH);
        // attention over io context vectors
        k_attn<<<NB, 128>>>();
        // classifier NLL accumulation
        k_cls<<<BATCH, 256>>>(b_comp, actions, out, t);
        // v-lstm gates = h @ v_Wh   (vXWi[t] + v_b added in k_dec_point)
        gemm_bf16<<<dim3(VG / BN, BATCH / BM, 1), 256>>>(
            p_hdec_bf, nullptr, p_vWh_bf, nullptr, p_gates_dec, nullptr,
            BATCH, VG, EH, EH, VG, VG);
        k_dec_point<<<(BATCH * EH) / 256, 256>>>(v_b, t);
    }
}

// round 4
// speedup vs baseline: 5.3008x; 1.1639x over previous
#include <cuda_runtime.h>
#include <cuda_bf16.h>
#include <mma.h>
#include <cstdint>
#include <cstddef>
using namespace nvcuda;

// ---------------- problem constants ----------------
#define LSEQ   64
#define BATCH  256
#define NIO    4
#define NB     1024      // BATCH*NIO
#define IO_EMB 128
#define XDIM   256       // 2*IO_EMB
#define HID    512       // IO_HID
#define GATE   2048      // 4*HID
#define KCAT   768       // XDIM + HID
#define EH     1024      // ENC_HID
#define VG     4096      // 4*EH
#define TDEC   32
#define NPROD  64
#define NDEC   5120      // EH + VG (combined decoder GEMM width)

// ---------------- device scratch (static, no allocs) ----------------
__device__ __nv_bfloat16 g_x[(size_t)LSEQ * NB * XDIM];
__device__ __nv_bfloat16 g_cat[2 * NB * KCAT];               // [dir][NB][768] = [x_t | h]
__device__ __nv_bfloat16 g_Wcat[2 * KCAT * GATE];            // interleaved: col = 4*u + gate
__device__ float g_h_enc[2 * NB * HID];
__device__ float g_c_enc[2 * NB * HID];
__device__ __nv_bfloat16 g_hs_f[(size_t)LSEQ * NB * HID];
__device__ __nv_bfloat16 g_hs_b[(size_t)LSEQ * NB * HID];
__device__ float g_h_dec[BATCH * EH];
__device__ float g_c_dec[BATCH * EH];
__device__ __nv_bfloat16 g_hdec_bf[BATCH * EH];
__device__ float g_qg[BATCH * NDEC];                         // [b][ q(1024) | gates(4096) ]
__device__ float g_ctx[NB * EH];
__device__ float g_vXWi[TDEC * VG];
__device__ __nv_bfloat16 g_Wdec[EH * NDEC];                  // [1024][ W_attn | v_Wh ]
__device__ __nv_bfloat16 g_vWi_bf[EH * VG];
__device__ __nv_bfloat16 g_field_bf[TDEC * EH];
__device__ __nv_bfloat16 g_Wcomp_bf[NPROD * 2048];           // transposed, bf16

__device__ __forceinline__ float sigf(float x) { return 1.f / (1.f + expf(-x)); }

// ---------------- cp.async helpers ----------------
__device__ __forceinline__ void cp16(void* dst, const void* src, bool valid) {
    unsigned int d = (unsigned int)__cvta_generic_to_shared(dst);
    int sz = valid ? 16 : 0;
    asm volatile("cp.async.cg.shared.global [%0], [%1], 16, %2;" :: "r"(d), "l"(src), "r"(sz));
}
__device__ __forceinline__ void cp_commit() { asm volatile("cp.async.commit_group;"); }
__device__ __forceinline__ void cp_wait1()  { asm volatile("cp.async.wait_group 1;"); }
__device__ __forceinline__ void cp_wait0()  { asm volatile("cp.async.wait_group 0;"); }

#define BM 128
#define BN 128
#define BK 32

// ---------------- plain bf16 tensor-core GEMM (decoder / setup) ----------------
__global__ void __launch_bounds__(256) gemm_bf16(
    const __nv_bfloat16* __restrict__ A, const __nv_bfloat16* __restrict__ B,
    float* __restrict__ C, int M, int N, int K, int lda, int ldb, int ldc)
{
    __shared__ __nv_bfloat16 As[2][BM][40];
    __shared__ __nv_bfloat16 Bs[2][BK][136];

    int tid  = threadIdx.x;
    int warp = tid >> 5;
    int wr = warp >> 1, wc = warp & 1;
    int brow = blockIdx.y * BM, bcol = blockIdx.x * BN;
    int m0 = wr * 32, n0 = wc * 64;

    wmma::fragment<wmma::accumulator, 16, 16, 16, float> acc[2][4];
#pragma unroll
    for (int i = 0; i < 2; i++)
#pragma unroll
        for (int j = 0; j < 4; j++)
            wmma::fill_fragment(acc[i][j], 0.f);

    int nk = K / BK;

    auto load_tile = [&](int buf, int k0) {
#pragma unroll
        for (int i = 0; i < 2; i++) {
            int cid = tid + i * 256;
            int row = cid >> 2;
            int col = (cid & 3) * 8;
            const __nv_bfloat16* src = A + (size_t)(brow + row) * lda + k0 + col;
            bool v = (brow + row) < M;
            cp16(&As[buf][row][col], v ? (const void*)src : (const void*)A, v);
        }
#pragma unroll
        for (int i = 0; i < 2; i++) {
            int cid = tid + i * 256;
            int row = cid >> 4;
            int col = (cid & 15) * 8;
            cp16(&Bs[buf][row][col], B + (size_t)(k0 + row) * ldb + bcol + col, true);
        }
    };

    load_tile(0, 0);
    cp_commit();

    int buf = 0;
    for (int kt = 0; kt < nk; kt++) {
        if (kt + 1 < nk) { load_tile(buf ^ 1, (kt + 1) * BK); cp_commit(); cp_wait1(); }
        else             { cp_wait0(); }
        __syncthreads();
#pragma unroll
        for (int kk = 0; kk < BK; kk += 16) {
            wmma::fragment<wmma::matrix_a, 16, 16, 16, __nv_bfloat16, wmma::row_major> af[2];
            wmma::fragment<wmma::matrix_b, 16, 16, 16, __nv_bfloat16, wmma::row_major> bfr[4];
#pragma unroll
            for (int i = 0; i < 2; i++)
                wmma::load_matrix_sync(af[i], &As[buf][m0 + i * 16][kk], 40);
#pragma unroll
            for (int j = 0; j < 4; j++)
                wmma::load_matrix_sync(bfr[j], &Bs[buf][kk][n0 + j * 16], 136);
#pragma unroll
            for (int i = 0; i < 2; i++)
#pragma unroll
                for (int j = 0; j < 4; j++)
                    wmma::mma_sync(acc[i][j], af[i], bfr[j], acc[i][j]);
        }
        __syncthreads();
        buf ^= 1;
    }

#pragma unroll
    for (int i = 0; i < 2; i++) {
        int gm = brow + m0 + i * 16;
        if (gm >= M) continue;
#pragma unroll
        for (int j = 0; j < 4; j++)
            wmma::store_matrix_sync(&C[(size_t)gm * ldc + bcol + n0 + j * 16],
                                    acc[i][j], ldc, wmma::mem_row_major);
    }
}

// ---------------- fused encoder step: GEMM + LSTM pointwise epilogue ----------------
// Weights interleaved: col n = 4*u + gate. Block (bx) owns units [bx*32, +32).
__global__ void __launch_bounds__(256) gemm_lstm(
    const float* __restrict__ b_f, const float* __restrict__ b_b, int s)
{
    extern __shared__ char dyn[];
    __nv_bfloat16 (*As)[BM][40]  = reinterpret_cast<__nv_bfloat16(*)[BM][40]>(dyn);
    __nv_bfloat16 (*Bs)[BK][136] = reinterpret_cast<__nv_bfloat16(*)[BK][136]>(dyn + 20480);

    int dir = blockIdx.z;
    const __nv_bfloat16* A = g_cat + (size_t)dir * NB * KCAT;
    const __nv_bfloat16* B = g_Wcat + (size_t)dir * KCAT * GATE;

    int tid  = threadIdx.x;
    int warp = tid >> 5;
    int wr = warp >> 1, wc = warp & 1;
    int brow = blockIdx.y * BM, bcol = blockIdx.x * BN;
    int m0 = wr * 32, n0 = wc * 64;

    wmma::fragment<wmma::accumulator, 16, 16, 16, float> acc[2][4];
#pragma unroll
    for (int i = 0; i < 2; i++)
#pragma unroll
        for (int j = 0; j < 4; j++)
            wmma::fill_fragment(acc[i][j], 0.f);

    auto load_tile = [&](int buf, int k0) {
#pragma unroll
        for (int i = 0; i < 2; i++) {
            int cid = tid + i * 256;
            int row = cid >> 2;
            int col = (cid & 3) * 8;
            cp16(&As[buf][row][col], A + (size_t)(brow + row) * KCAT + k0 + col, true);
        }
#pragma unroll
        for (int i = 0; i < 2; i++) {
            int cid = tid + i * 256;
            int row = cid >> 4;
            int col = (cid & 15) * 8;
            cp16(&Bs[buf][row][col], B + (size_t)(k0 + row) * GATE + bcol + col, true);
        }
    };

    const int nk = KCAT / BK;   // 24
    load_tile(0, 0);
    cp_commit();

    int buf = 0;
    for (int kt = 0; kt < nk; kt++) {
        if (kt + 1 < nk) { load_tile(buf ^ 1, (kt + 1) * BK); cp_commit(); cp_wait1(); }
        else             { cp_wait0(); }
        __syncthreads();
#pragma unroll
        for (int kk = 0; kk < BK; kk += 16) {
            wmma::fragment<wmma::matrix_a, 16, 16, 16, __nv_bfloat16, wmma::row_major> af[2];
            wmma::fragment<wmma::matrix_b, 16, 16, 16, __nv_bfloat16, wmma::row_major> bfr[4];
#pragma unroll
            for (int i = 0; i < 2; i++)
                wmma::load_matrix_sync(af[i], &As[buf][m0 + i * 16][kk], 40);
#pragma unroll
            for (int j = 0; j < 4; j++)
                wmma::load_matrix_sync(bfr[j], &Bs[buf][kk][n0 + j * 16], 136);
#pragma unroll
            for (int i = 0; i < 2; i++)
#pragma unroll
                for (int j = 0; j < 4; j++)
                    wmma::mma_sync(acc[i][j], af[i], bfr[j], acc[i][j]);
        }
        __syncthreads();
        buf ^= 1;
    }

    // ---- epilogue: stage gates to smem, apply LSTM pointwise ----
    float* Cs = reinterpret_cast<float*>(dyn);   // [128][132]
#pragma unroll
    for (int i = 0; i < 2; i++)
#pragma unroll
        for (int j = 0; j < 4; j++)
            wmma::store_matrix_sync(&Cs[(m0 + i * 16) * 132 + n0 + j * 16],
                                    acc[i][j], 132, wmma::mem_row_major);
    __syncthreads();

    const float* bias = dir ? b_b : b_f;
    int t = dir ? (LSEQ - 1 - s) : s;
    __nv_bfloat16* hsdst = dir ? g_hs_b : g_hs_f;

    for (int task = tid; task < 128 * 32; task += 256) {
        int r  = task >> 5;       // local row
        int jl = task & 31;       // local unit
        int nb = brow + r;
        int u  = (bcol >> 2) + jl;
        float gi = Cs[r * 132 + jl * 4 + 0] + bias[u];
        float gf = Cs[r * 132 + jl * 4 + 1] + bias[512 + u];
        float gg = Cs[r * 132 + jl * 4 + 2] + bias[1024 + u];
        float go = Cs[r * 132 + jl * 4 + 3] + bias[1536 + u];
        size_t cidx = ((size_t)dir * NB + nb) * HID + u;
        float c = g_c_enc[cidx];
        c = sigf(gf) * c + sigf(gi) * tanhf(gg);
        float h = sigf(go) * tanhf(c);
        g_c_enc[cidx] = c;
        if (s == LSEQ - 1) g_h_enc[cidx] = h;
        __nv_bfloat16 hb = __float2bfloat16(h);
        hsdst[((size_t)t * NB + nb) * HID + u] = hb;
        g_cat[((size_t)dir * NB + nb) * KCAT + XDIM + u] = hb;
    }

    // x-column refresh for next step (bx==0 blocks own it)
    if (blockIdx.x == 0) {
        int tn = dir ? (LSEQ - 2 - s) : (s + 1);
        if (tn >= 0 && tn < LSEQ) {
            for (int e = tid; e < 128 * 64; e += 256) {   // uint2 = 4 bf16
                int r = e >> 6, cc = e & 63;
                int nb = brow + r;
                ((uint2*)(g_cat + ((size_t)dir * NB + nb) * KCAT))[cc] =
                ((const uint2*)(g_x + ((size_t)tn * NB + nb) * XDIM))[cc];
            }
        }
    }
}

// ---------------- setup kernels ----------------
__global__ void k_embed(const int* __restrict__ exs, const int* __restrict__ cls,
                        const float* __restrict__ E) {
    int idx = blockIdx.x * blockDim.x + threadIdx.x;
    int j  = idx & (XDIM - 1);
    int tn = idx >> 8;
    int tok = (j < IO_EMB) ? exs[tn] : cls[tn];
    int jj  = (j < IO_EMB) ? j : j - IO_EMB;
    g_x[idx] = __float2bfloat16(E[tok * IO_EMB + jj]);
}

__global__ void k_wcat(const float* __restrict__ Wi_f, const float* __restrict__ Wh_f,
                       const float* __restrict__ Wi_b, const float* __restrict__ Wh_b) {
    int idx = blockIdx.x * blockDim.x + threadIdx.x;   // 2*KCAT*GATE
    int dir = idx / (KCAT * GATE);
    int r   = idx - dir * (KCAT * GATE);
    int k   = r / GATE;
    int n   = r - k * GATE;          // interleaved col: n = 4*u + gate
    int u = n >> 2, g = n & 3;
    int col_orig = g * 512 + u;
    const float* src;
    int kk;
    if (k < XDIM) { src = dir ? Wi_b : Wi_f; kk = k; }
    else          { src = dir ? Wh_b : Wh_f; kk = k - XDIM; }
    g_Wcat[idx] = __float2bfloat16(src[kk * GATE + col_orig]);
}

__global__ void k_conv(const float* __restrict__ W_attn, const float* __restrict__ v_Wi,
                       const float* __restrict__ v_Wh, const float* __restrict__ field,
                       const float* __restrict__ W_comp, float* __restrict__ out) {
    int idx = blockIdx.x * blockDim.x + threadIdx.x;   // EH*NDEC threads
    if (idx < EH * NDEC) {
        int k = idx / NDEC, n = idx - k * NDEC;
        float v = (n < EH) ? W_attn[k * EH + n] : v_Wh[k * VG + (n - EH)];
        g_Wdec[idx] = __float2bfloat16(v);
    }
    if (idx < EH * VG)      g_vWi_bf[idx] = __float2bfloat16(v_Wi[idx]);
    if (idx < TDEC * EH)    g_field_bf[idx] = __float2bfloat16(field[idx]);
    if (idx < NPROD * 2048) {
        int j = idx / 2048, k = idx - j * 2048;
        g_Wcomp_bf[idx] = __float2bfloat16(W_comp[k * NPROD + j]);
    }
    if (idx < BATCH) out[idx] = 0.f;
}

__global__ void k_init() {
    int idx = blockIdx.x * blockDim.x + threadIdx.x;   // 2*NB*KCAT
    int dir = idx / (NB * KCAT);
    int r   = idx - dir * (NB * KCAT);
    int nb  = r / KCAT;
    int col = r - nb * KCAT;
    if (col < XDIM) {
        int t0 = dir ? (LSEQ - 1) : 0;
        g_cat[idx] = g_x[((size_t)t0 * NB + nb) * XDIM + col];
    } else {
        g_cat[idx] = __float2bfloat16(0.f);
    }
    if (idx < 2 * NB * HID) g_c_enc[idx] = 0.f;
}

// ---------------- pool final encoder states -> decoder init ----------------
__global__ void k_pool() {
    int idx = blockIdx.x * blockDim.x + threadIdx.x;   // BATCH*EH
    int b = idx >> 10;
    int e = idx & 1023;
    int base = (e < 512) ? 0 : NB * HID;
    int ee   = (e < 512) ? e : e - 512;
    float hm = -1e30f, cm = -1e30f;
#pragma unroll
    for (int n = 0; n < 4; n++) {
        int off = base + (b * 4 + n) * HID + ee;
        hm = fmaxf(hm, g_h_enc[off]);
        cm = fmaxf(cm, g_c_enc[off]);
    }
    g_h_dec[idx] = hm;
    g_c_dec[idx] = cm;
    g_hdec_bf[idx] = __float2bfloat16(hm);
}

// ---------------- attention: warp-parallel online softmax over L ----------------
__global__ void __launch_bounds__(128) k_attn() {
    int nb = blockIdx.x;
    int b  = nb >> 2;
    int tid = threadIdx.x, lane = tid & 31, warp = tid >> 5;

    __shared__ float s_acc[4][1024];
    __shared__ float s_m[4], s_s[4];

    // q registers: 4 chunks x 8 floats; dim = c*256 + lane*8 + i
    const float* q = g_qg + (size_t)b * NDEC;
    float qr[4][8];
#pragma unroll
    for (int c = 0; c < 4; c++) {
        float4 x0 = *(const float4*)&q[c * 256 + lane * 8];
        float4 x1 = *(const float4*)&q[c * 256 + lane * 8 + 4];
        qr[c][0] = x0.x; qr[c][1] = x0.y; qr[c][2] = x0.z; qr[c][3] = x0.w;
        qr[c][4] = x1.x; qr[c][5] = x1.y; qr[c][6] = x1.z; qr[c][7] = x1.w;
    }

    float m = -1e30f, s = 0.f;
    float acc[4][8] = {};

    for (int li = 0; li < 16; li++) {
        int l = warp + li * 4;
        const __nv_bfloat16* pf = g_hs_f + ((size_t)l * NB + nb) * HID;
        const __nv_bfloat16* pb = g_hs_b + ((size_t)l * NB + nb) * HID;
        uint4 d[4];
        d[0] = *(const uint4*)&pf[lane * 8];
        d[1] = *(const uint4*)&pf[256 + lane * 8];
        d[2] = *(const uint4*)&pb[lane * 8];
        d[3] = *(const uint4*)&pb[256 + lane * 8];
        float v[4][8];
#pragma unroll
        for (int c = 0; c < 4; c++) {
            const unsigned int* w = (const unsigned int*)&d[c];
#pragma unroll
            for (int h = 0; h < 4; h++) {
                float2 f2 = __bfloat1622float2(*reinterpret_cast<const __nv_bfloat162*>(&w[h]));
                v[c][h * 2]     = f2.x;
                v[c][h * 2 + 1] = f2.y;
            }
        }
        float p = 0.f;
#pragma unroll
        for (int c = 0; c < 4; c++)
#pragma unroll
            for (int i = 0; i < 8; i++)
                p += v[c][i] * qr[c][i];
#pragma unroll
        for (int off = 16; off > 0; off >>= 1)
            p += __shfl_xor_sync(0xffffffffu, p, off);

        float mn = fmaxf(m, p);
        float sc = __expf(m - mn);
        float p2 = __expf(p - mn);
        s = s * sc + p2;
#pragma unroll
        for (int c = 0; c < 4; c++)
#pragma unroll
            for (int i = 0; i < 8; i++)
                acc[c][i] = acc[c][i] * sc + p2 * v[c][i];
        m = mn;
    }

    if (lane == 0) { s_m[warp] = m; s_s[warp] = s; }
#pragma unroll
    for (int c = 0; c < 4; c++)
#pragma unroll
        for (int i = 0; i < 8; i++)
            s_acc[warp][c * 256 + lane * 8 + i] = acc[c][i];
    __syncthreads();

    float M = fmaxf(fmaxf(s_m[0], s_m[1]), fmaxf(s_m[2], s_m[3]));
    float e0 = __expf(s_m[0] - M), e1 = __expf(s_m[1] - M);
    float e2 = __expf(s_m[2] - M), e3 = __expf(s_m[3] - M);
    float S = s_s[0] * e0 + s_s[1] * e1 + s_s[2] * e2 + s_s[3] * e3;
    float inv = 1.f / S;

    float* ctx = g_ctx + (size_t)nb * EH;
    int d0 = tid * 8;
#pragma unroll
    for (int i = 0; i < 8; i++) {
        int d = d0 + i;
        ctx[d] = (s_acc[0][d] * e0 + s_acc[1][d] * e1 +
                  s_acc[2][d] * e2 + s_acc[3][d] * e3) * inv;
    }
}

// ---------------- classifier NLL + decoder LSTM pointwise (fused) ----------------
__global__ void __launch_bounds__(256) k_cls_point(
    const float* __restrict__ b_comp, const int* __restrict__ actions,
    const float* __restrict__ v_b, float* __restrict__ out, int t)
{
    int b = blockIdx.x;
    int tid = threadIdx.x;
    int lane = tid & 31, warp = tid >> 5;
    __shared__ float feat[2048];
    __shared__ float lg[NPROD];

    for (int e = tid; e < 2048; e += 256) {
        float v;
        if (e < 1024) {
            v = g_h_dec[(size_t)b * EH + e];
        } else {
            int ee = e - 1024;
            float m0 = g_ctx[(size_t)(b * 4 + 0) * EH + ee];
            float m1 = g_ctx[(size_t)(b * 4 + 1) * EH + ee];
            float m2 = g_ctx[(size_t)(b * 4 + 2) * EH + ee];
            float m3 = g_ctx[(size_t)(b * 4 + 3) * EH + ee];
            v = fmaxf(fmaxf(m0, m1), fmaxf(m2, m3));
        }
        feat[e] = v;
    }
    __syncthreads();

    for (int j = warp; j < NPROD; j += 8) {
        const __nv_bfloat16* w = g_Wcomp_bf + (size_t)j * 2048;
        float p = 0.f;
        for (int k = lane * 8; k < 2048; k += 256) {
            uint4 d = *(const uint4*)&w[k];
            const unsigned int* wd = (const unsigned int*)&d;
#pragma unroll
            for (int h = 0; h < 4; h++) {
                float2 f2 = __bfloat1622float2(*reinterpret_cast<const __nv_bfloat162*>(&wd[h]));
                p += f2.x * feat[k + h * 2] + f2.y * feat[k + h * 2 + 1];
            }
        }
#pragma unroll
        for (int off = 16; off > 0; off >>= 1)
            p += __shfl_down_sync(0xffffffffu, p, off);
        if (lane == 0) lg[j] = p + b_comp[j];
    }
    __syncthreads();
    if (tid == 0) {
        float mx = -1e30f;
        for (int j = 0; j < NPROD; j++) mx = fmaxf(mx, lg[j]);
        float sum = 0.f;
        for (int j = 0; j < NPROD; j++) sum += __expf(lg[j] - mx);
        float lse = mx + __logf(sum);
        int a = actions[b * TDEC + t];
        out[b] += lse - lg[a];
    }

    // decoder LSTM pointwise for this b (h reads done above via feat)
    const float* gates = g_qg + (size_t)b * NDEC + EH;
    const float* xg = g_vXWi + (size_t)t * VG;
    for (int u = tid; u < EH; u += 256) {
        float gi = gates[u]          + xg[u]          + v_b[u];
        float gf = gates[EH + u]     + xg[EH + u]     + v_b[EH + u];
        float gg = gates[2 * EH + u] + xg[2 * EH + u] + v_b[2 * EH + u];
        float go = gates[3 * EH + u] + xg[3 * EH + u] + v_b[3 * EH + u];
        size_t idx = (size_t)b * EH + u;
        float c = g_c_dec[idx];
        c = sigf(gf) * c + sigf(gi) * tanhf(gg);
        float h = sigf(go) * tanhf(c);
        g_c_dec[idx] = c;
        g_h_dec[idx] = h;
        g_hdec_bf[idx] = __float2bfloat16(h);
    }
}

// ---------------- host orchestration ----------------
extern "C" void kernel_launch(void* const* d_in, const int* in_sizes, int n_in,
                              void* d_out, int out_size) {
    const int*   exs     = (const int*)  d_in[0];
    const int*   cls     = (const int*)  d_in[1];
    const float* E       = (const float*)d_in[2];
    const float* Wi_f    = (const float*)d_in[3];
    const float* Wh_f    = (const float*)d_in[4];
    const float* b_f     = (const float*)d_in[5];
    const float* Wi_b    = (const float*)d_in[6];
    const float* Wh_b    = (const float*)d_in[7];
    const float* b_b     = (const float*)d_in[8];
    const float* W_attn  = (const float*)d_in[9];
    const float* W_comp  = (const float*)d_in[10];
    const float* b_comp  = (const float*)d_in[11];
    const float* v_Wi    = (const float*)d_in[12];
    const float* v_Wh    = (const float*)d_in[13];
    const float* v_b     = (const float*)d_in[14];
    const float* field   = (const float*)d_in[15];
    const int*   actions = (const int*)  d_in[16];
    float* out = (float*)d_out;

    const int DYN = 128 * 132 * 4;   // 67584 bytes for fused epilogue
    cudaFuncSetAttribute(gemm_lstm, cudaFuncAttributeMaxDynamicSharedMemorySize, DYN);

    __nv_bfloat16 *p_hdec_bf, *p_vWi_bf, *p_field_bf, *p_Wdec;
    float *p_qg, *p_vXWi;
    cudaGetSymbolAddress((void**)&p_hdec_bf, g_hdec_bf);
    cudaGetSymbolAddress((void**)&p_vWi_bf, g_vWi_bf);
    cudaGetSymbolAddress((void**)&p_field_bf, g_field_bf);
    cudaGetSymbolAddress((void**)&p_Wdec, g_Wdec);
    cudaGetSymbolAddress((void**)&p_qg, g_qg);
    cudaGetSymbolAddress((void**)&p_vXWi, g_vXWi);

    // ---- setup ----
    k_embed<<<(LSEQ * NB * XDIM) / 256, 256>>>(exs, cls, E);
    k_wcat<<<(2 * KCAT * GATE) / 256, 256>>>(Wi_f, Wh_f, Wi_b, Wh_b);
    k_conv<<<(EH * NDEC) / 256, 256>>>(W_attn, v_Wi, v_Wh, field, W_comp, out);
    k_init<<<(2 * NB * KCAT) / 256, 256>>>();

    // vXWi = field_emb @ v_Wi   [32, 4096]
    gemm_bf16<<<dim3(VG / BN, 1, 1), 256>>>(
        p_field_bf, p_vWi_bf, p_vXWi, TDEC, VG, EH, EH, VG, VG);

    // ---- biLSTM encoder: 64 fused steps ----
    for (int s = 0; s < LSEQ; s++)
        gemm_lstm<<<dim3(GATE / BN, NB / BM, 2), 256, DYN>>>(b_f, b_b, s);

    // ---- decoder init ----
    k_pool<<<(BATCH * EH) / 256, 256>>>();

    // ---- decoder: 32 steps ----
    for (int t = 0; t < TDEC; t++) {
        // [q | gates] = h @ [W_attn | v_Wh]
        gemm_bf16<<<dim3(NDEC / BN, BATCH / BM, 1), 256>>>(
            p_hdec_bf, p_Wdec, p_qg, BATCH, NDEC, EH, EH, NDEC, NDEC);
        k_attn<<<NB, 128>>>();
        k_cls_point<<<BATCH, 256>>>(b_comp, actions, v_b, out, t);
    }
}

// round 5
// speedup vs baseline: 7.3949x; 1.3950x over previous
#include <cuda_runtime.h>
#include <cuda_bf16.h>
#include <mma.h>
#include <cstdint>
#include <cstddef>
using namespace nvcuda;

// ---------------- problem constants ----------------
#define LSEQ   64
#define BATCH  256
#define NIO    4
#define NB     1024      // BATCH*NIO
#define IO_EMB 128
#define XDIM   256       // 2*IO_EMB
#define HID    512       // IO_HID
#define GATE   2048      // 4*HID
#define KCAT   768       // XDIM + HID
#define EH     1024      // ENC_HID
#define VG     4096      // 4*EH
#define TDEC   32
#define NPROD  64
#define TB     (TDEC * BATCH)   // 8192

// ---------------- device scratch (static, no allocs) ----------------
__device__ __nv_bfloat16 g_x[(size_t)LSEQ * NB * XDIM];
__device__ __nv_bfloat16 g_cat[2 * NB * KCAT];
__device__ __nv_bfloat16 g_Wcat[2 * KCAT * GATE];            // interleaved: col = 4*u + gate
__device__ float g_h_enc[2 * NB * HID];
__device__ float g_c_enc[2 * NB * HID];
__device__ __nv_bfloat16 g_hs_f[(size_t)LSEQ * NB * HID];
__device__ __nv_bfloat16 g_hs_b[(size_t)LSEQ * NB * HID];
__device__ float g_c_dec[BATCH * EH];
__device__ __nv_bfloat16 g_hdec_bf[2 * BATCH * EH];          // parity double buffer
__device__ __nv_bfloat16 g_feat[(size_t)TB * 2048];          // [t*256+b][ h(1024) | ctxp(1024) ]
__device__ float g_q_all[(size_t)TB * EH];
__device__ float g_ctx_all[(size_t)TDEC * NB * EH];          // 134 MB
__device__ float g_vXWi[TDEC * VG];                          // interleaved gates
__device__ __nv_bfloat16 g_Wattn_bf[EH * EH];
__device__ __nv_bfloat16 g_vWi_bf[EH * VG];                  // interleaved
__device__ __nv_bfloat16 g_vWh_bf[EH * VG];                  // interleaved
__device__ __nv_bfloat16 g_field_bf[TDEC * EH];
__device__ __nv_bfloat16 g_Wcls_bf[2048 * NPROD];            // native W_comp layout
__device__ float g_logits[(size_t)TB * NPROD];
__device__ float g_nll[TB];

__device__ __forceinline__ float sigf(float x) { return 1.f / (1.f + expf(-x)); }

// ---------------- cp.async helpers ----------------
__device__ __forceinline__ void cp16(void* dst, const void* src, bool valid) {
    unsigned int d = (unsigned int)__cvta_generic_to_shared(dst);
    int sz = valid ? 16 : 0;
    asm volatile("cp.async.cg.shared.global [%0], [%1], 16, %2;" :: "r"(d), "l"(src), "r"(sz));
}
__device__ __forceinline__ void cp_commit() { asm volatile("cp.async.commit_group;"); }
__device__ __forceinline__ void cp_wait1()  { asm volatile("cp.async.wait_group 1;"); }
__device__ __forceinline__ void cp_wait0()  { asm volatile("cp.async.wait_group 0;"); }

#define BM 128
#define BN 128
#define BK 32

// ---------------- 128x128 bf16 tensor-core GEMM ----------------
__global__ void __launch_bounds__(256) gemm_bf16(
    const __nv_bfloat16* __restrict__ A, const __nv_bfloat16* __restrict__ B,
    float* __restrict__ C, int M, int N, int K, int lda, int ldb, int ldc)
{
    __shared__ __nv_bfloat16 As[2][BM][40];
    __shared__ __nv_bfloat16 Bs[2][BK][136];

    int tid  = threadIdx.x;
    int warp = tid >> 5;
    int wr = warp >> 1, wc = warp & 1;
    int brow = blockIdx.y * BM, bcol = blockIdx.x * BN;
    int m0 = wr * 32, n0 = wc * 64;

    wmma::fragment<wmma::accumulator, 16, 16, 16, float> acc[2][4];
#pragma unroll
    for (int i = 0; i < 2; i++)
#pragma unroll
        for (int j = 0; j < 4; j++)
            wmma::fill_fragment(acc[i][j], 0.f);

    int nk = K / BK;

    auto load_tile = [&](int buf, int k0) {
#pragma unroll
        for (int i = 0; i < 2; i++) {
            int cid = tid + i * 256;
            int row = cid >> 2;
            int col = (cid & 3) * 8;
            const __nv_bfloat16* src = A + (size_t)(brow + row) * lda + k0 + col;
            bool v = (brow + row) < M;
            cp16(&As[buf][row][col], v ? (const void*)src : (const void*)A, v);
        }
#pragma unroll
        for (int i = 0; i < 2; i++) {
            int cid = tid + i * 256;
            int row = cid >> 4;
            int col = (cid & 15) * 8;
            cp16(&Bs[buf][row][col], B + (size_t)(k0 + row) * ldb + bcol + col, true);
        }
    };

    load_tile(0, 0);
    cp_commit();

    int buf = 0;
    for (int kt = 0; kt < nk; kt++) {
        if (kt + 1 < nk) { load_tile(buf ^ 1, (kt + 1) * BK); cp_commit(); cp_wait1(); }
        else             { cp_wait0(); }
        __syncthreads();
#pragma unroll
        for (int kk = 0; kk < BK; kk += 16) {
            wmma::fragment<wmma::matrix_a, 16, 16, 16, __nv_bfloat16, wmma::row_major> af[2];
            wmma::fragment<wmma::matrix_b, 16, 16, 16, __nv_bfloat16, wmma::row_major> bfr[4];
#pragma unroll
            for (int i = 0; i < 2; i++)
                wmma::load_matrix_sync(af[i], &As[buf][m0 + i * 16][kk], 40);
#pragma unroll
            for (int j = 0; j < 4; j++)
                wmma::load_matrix_sync(bfr[j], &Bs[buf][kk][n0 + j * 16], 136);
#pragma unroll
            for (int i = 0; i < 2; i++)
#pragma unroll
                for (int j = 0; j < 4; j++)
                    wmma::mma_sync(acc[i][j], af[i], bfr[j], acc[i][j]);
        }
        __syncthreads();
        buf ^= 1;
    }

#pragma unroll
    for (int i = 0; i < 2; i++) {
        int gm = brow + m0 + i * 16;
        if (gm >= M) continue;
#pragma unroll
        for (int j = 0; j < 4; j++)
            wmma::store_matrix_sync(&C[(size_t)gm * ldc + bcol + n0 + j * 16],
                                    acc[i][j], ldc, wmma::mem_row_major);
    }
}

// ---------------- 64x64 bf16 GEMM (narrow matrices), plain ----------------
__global__ void __launch_bounds__(128) gemm64(
    const __nv_bfloat16* __restrict__ A, const __nv_bfloat16* __restrict__ B,
    float* __restrict__ C, int K, int lda, int ldb, int ldc)
{
    __shared__ __nv_bfloat16 As[2][64][40];
    __shared__ __nv_bfloat16 Bs[2][32][72];

    int tid = threadIdx.x, warp = tid >> 5;
    int m0 = (warp & 1) * 32, n0 = (warp >> 1) * 32;
    int brow = blockIdx.y * 64, bcol = blockIdx.x * 64;

    wmma::fragment<wmma::accumulator, 16, 16, 16, float> acc[2][2];
#pragma unroll
    for (int i = 0; i < 2; i++)
#pragma unroll
        for (int j = 0; j < 2; j++)
            wmma::fill_fragment(acc[i][j], 0.f);

    auto load_tile = [&](int buf, int k0) {
#pragma unroll
        for (int i = 0; i < 2; i++) {
            int cid = tid + i * 128;
            int row = cid >> 2, col = (cid & 3) * 8;
            cp16(&As[buf][row][col], A + (size_t)(brow + row) * lda + k0 + col, true);
        }
#pragma unroll
        for (int i = 0; i < 2; i++) {
            int cid = tid + i * 128;
            int row = cid >> 3, col = (cid & 7) * 8;
            cp16(&Bs[buf][row][col], B + (size_t)(k0 + row) * ldb + bcol + col, true);
        }
    };

    int nk = K / 32;
    load_tile(0, 0);
    cp_commit();
    int buf = 0;
    for (int kt = 0; kt < nk; kt++) {
        if (kt + 1 < nk) { load_tile(buf ^ 1, (kt + 1) * 32); cp_commit(); cp_wait1(); }
        else             { cp_wait0(); }
        __syncthreads();
#pragma unroll
        for (int kk = 0; kk < 32; kk += 16) {
            wmma::fragment<wmma::matrix_a, 16, 16, 16, __nv_bfloat16, wmma::row_major> af[2];
            wmma::fragment<wmma::matrix_b, 16, 16, 16, __nv_bfloat16, wmma::row_major> bfr[2];
#pragma unroll
            for (int i = 0; i < 2; i++)
                wmma::load_matrix_sync(af[i], &As[buf][m0 + i * 16][kk], 40);
#pragma unroll
            for (int j = 0; j < 2; j++)
                wmma::load_matrix_sync(bfr[j], &Bs[buf][kk][n0 + j * 16], 72);
#pragma unroll
            for (int i = 0; i < 2; i++)
#pragma unroll
                for (int j = 0; j < 2; j++)
                    wmma::mma_sync(acc[i][j], af[i], bfr[j], acc[i][j]);
        }
        __syncthreads();
        buf ^= 1;
    }
#pragma unroll
    for (int i = 0; i < 2; i++)
#pragma unroll
        for (int j = 0; j < 2; j++)
            wmma::store_matrix_sync(&C[(size_t)(brow + m0 + i * 16) * ldc + bcol + n0 + j * 16],
                                    acc[i][j], ldc, wmma::mem_row_major);
}

// ---------------- Phase A: fused v-LSTM step (64x64 tiles + pointwise) ----------------
// gates = hdec[par] @ vWh(interleaved) ; h_next -> hdec[par^1], g_feat[t+1]
__global__ void __launch_bounds__(128) gemm_vlstm(const float* __restrict__ v_b, int t) {
    __shared__ __nv_bfloat16 As[2][64][40];
    __shared__ __nv_bfloat16 Bs[2][32][72];
    __shared__ float Cs[64][68];

    int par = t & 1;
    const __nv_bfloat16* A = g_hdec_bf + (size_t)par * BATCH * EH;
    __nv_bfloat16* hout = g_hdec_bf + (size_t)(par ^ 1) * BATCH * EH;

    int tid = threadIdx.x, warp = tid >> 5;
    int m0 = (warp & 1) * 32, n0 = (warp >> 1) * 32;
    int brow = blockIdx.y * 64, bcol = blockIdx.x * 64;

    wmma::fragment<wmma::accumulator, 16, 16, 16, float> acc[2][2];
#pragma unroll
    for (int i = 0; i < 2; i++)
#pragma unroll
        for (int j = 0; j < 2; j++)
            wmma::fill_fragment(acc[i][j], 0.f);

    auto load_tile = [&](int buf, int k0) {
#pragma unroll
        for (int i = 0; i < 2; i++) {
            int cid = tid + i * 128;
            int row = cid >> 2, col = (cid & 3) * 8;
            cp16(&As[buf][row][col], A + (size_t)(brow + row) * EH + k0 + col, true);
        }
#pragma unroll
        for (int i = 0; i < 2; i++) {
            int cid = tid + i * 128;
            int row = cid >> 3, col = (cid & 7) * 8;
            cp16(&Bs[buf][row][col], g_vWh_bf + (size_t)(k0 + row) * VG + bcol + col, true);
        }
    };

    load_tile(0, 0);
    cp_commit();
    int buf = 0;
    for (int kt = 0; kt < EH / 32; kt++) {
        if (kt + 1 < EH / 32) { load_tile(buf ^ 1, (kt + 1) * 32); cp_commit(); cp_wait1(); }
        else                  { cp_wait0(); }
        __syncthreads();
#pragma unroll
        for (int kk = 0; kk < 32; kk += 16) {
            wmma::fragment<wmma::matrix_a, 16, 16, 16, __nv_bfloat16, wmma::row_major> af[2];
            wmma::fragment<wmma::matrix_b, 16, 16, 16, __nv_bfloat16, wmma::row_major> bfr[2];
#pragma unroll
            for (int i = 0; i < 2; i++)
                wmma::load_matrix_sync(af[i], &As[buf][m0 + i * 16][kk], 40);
#pragma unroll
            for (int j = 0; j < 2; j++)
                wmma::load_matrix_sync(bfr[j], &Bs[buf][kk][n0 + j * 16], 72);
#pragma unroll
            for (int i = 0; i < 2; i++)
#pragma unroll
                for (int j = 0; j < 2; j++)
                    wmma::mma_sync(acc[i][j], af[i], bfr[j], acc[i][j]);
        }
        __syncthreads();
        buf ^= 1;
    }
#pragma unroll
    for (int i = 0; i < 2; i++)
#pragma unroll
        for (int j = 0; j < 2; j++)
            wmma::store_matrix_sync(&Cs[m0 + i * 16][n0 + j * 16], acc[i][j], 68,
                                    wmma::mem_row_major);
    __syncthreads();

    // pointwise: block owns 16 units x 64 rows
    const float* xg = g_vXWi + (size_t)t * VG;
    for (int task = tid; task < 64 * 16; task += 128) {
        int r = task >> 4, ju = task & 15;
        int b = brow + r;
        int u = (bcol >> 2) + ju;
        float gi = Cs[r][ju * 4 + 0] + xg[(u << 2) + 0] + v_b[u];
        float gf = Cs[r][ju * 4 + 1] + xg[(u << 2) + 1] + v_b[EH + u];
        float gg = Cs[r][ju * 4 + 2] + xg[(u << 2) + 2] + v_b[2 * EH + u];
        float go = Cs[r][ju * 4 + 3] + xg[(u << 2) + 3] + v_b[3 * EH + u];
        size_t ci = (size_t)b * EH + u;
        float c = g_c_dec[ci];
        c = sigf(gf) * c + sigf(gi) * tanhf(gg);
        float h = sigf(go) * tanhf(c);
        g_c_dec[ci] = c;
        __nv_bfloat16 hb = __float2bfloat16(h);
        hout[ci] = hb;
        g_feat[((size_t)(t + 1) * BATCH + b) * 2048 + u] = hb;
    }
}

// ---------------- fused encoder step: GEMM + LSTM pointwise epilogue ----------------
__global__ void __launch_bounds__(256) gemm_lstm(
    const float* __restrict__ b_f, const float* __restrict__ b_b, int s)
{
    extern __shared__ char dyn[];
    __nv_bfloat16 (*As)[BM][40]  = reinterpret_cast<__nv_bfloat16(*)[BM][40]>(dyn);
    __nv_bfloat16 (*Bs)[BK][136] = reinterpret_cast<__nv_bfloat16(*)[BK][136]>(dyn + 20480);

    int dir = blockIdx.z;
    const __nv_bfloat16* A = g_cat + (size_t)dir * NB * KCAT;
    const __nv_bfloat16* B = g_Wcat + (size_t)dir * KCAT * GATE;

    int tid  = threadIdx.x;
    int warp = tid >> 5;
    int wr = warp >> 1, wc = warp & 1;
    int brow = blockIdx.y * BM, bcol = blockIdx.x * BN;
    int m0 = wr * 32, n0 = wc * 64;

    wmma::fragment<wmma::accumulator, 16, 16, 16, float> acc[2][4];
#pragma unroll
    for (int i = 0; i < 2; i++)
#pragma unroll
        for (int j = 0; j < 4; j++)
            wmma::fill_fragment(acc[i][j], 0.f);

    auto load_tile = [&](int buf, int k0) {
#pragma unroll
        for (int i = 0; i < 2; i++) {
            int cid = tid + i * 256;
            int row = cid >> 2, col = (cid & 3) * 8;
            cp16(&As[buf][row][col], A + (size_t)(brow + row) * KCAT + k0 + col, true);
        }
#pragma unroll
        for (int i = 0; i < 2; i++) {
            int cid = tid + i * 256;
            int row = cid >> 4, col = (cid & 15) * 8;
            cp16(&Bs[buf][row][col], B + (size_t)(k0 + row) * GATE + bcol + col, true);
        }
    };

    const int nk = KCAT / BK;
    load_tile(0, 0);
    cp_commit();
    int buf = 0;
    for (int kt = 0; kt < nk; kt++) {
        if (kt + 1 < nk) { load_tile(buf ^ 1, (kt + 1) * BK); cp_commit(); cp_wait1(); }
        else             { cp_wait0(); }
        __syncthreads();
#pragma unroll
        for (int kk = 0; kk < BK; kk += 16) {
            wmma::fragment<wmma::matrix_a, 16, 16, 16, __nv_bfloat16, wmma::row_major> af[2];
            wmma::fragment<wmma::matrix_b, 16, 16, 16, __nv_bfloat16, wmma::row_major> bfr[4];
#pragma unroll
            for (int i = 0; i < 2; i++)
                wmma::load_matrix_sync(af[i], &As[buf][m0 + i * 16][kk], 40);
#pragma unroll
            for (int j = 0; j < 4; j++)
                wmma::load_matrix_sync(bfr[j], &Bs[buf][kk][n0 + j * 16], 136);
#pragma unroll
            for (int i = 0; i < 2; i++)
#pragma unroll
                for (int j = 0; j < 4; j++)
                    wmma::mma_sync(acc[i][j], af[i], bfr[j], acc[i][j]);
        }
        __syncthreads();
        buf ^= 1;
    }

    float* Cs = reinterpret_cast<float*>(dyn);   // [128][132]
#pragma unroll
    for (int i = 0; i < 2; i++)
#pragma unroll
        for (int j = 0; j < 4; j++)
            wmma::store_matrix_sync(&Cs[(m0 + i * 16) * 132 + n0 + j * 16],
                                    acc[i][j], 132, wmma::mem_row_major);
    __syncthreads();

    const float* bias = dir ? b_b : b_f;
    int t = dir ? (LSEQ - 1 - s) : s;
    __nv_bfloat16* hsdst = dir ? g_hs_b : g_hs_f;

    for (int task = tid; task < 128 * 32; task += 256) {
        int r  = task >> 5;
        int jl = task & 31;
        int nb = brow + r;
        int u  = (bcol >> 2) + jl;
        float gi = Cs[r * 132 + jl * 4 + 0] + bias[u];
        float gf = Cs[r * 132 + jl * 4 + 1] + bias[512 + u];
        float gg = Cs[r * 132 + jl * 4 + 2] + bias[1024 + u];
        float go = Cs[r * 132 + jl * 4 + 3] + bias[1536 + u];
        size_t cidx = ((size_t)dir * NB + nb) * HID + u;
        float c = g_c_enc[cidx];
        c = sigf(gf) * c + sigf(gi) * tanhf(gg);
        float h = sigf(go) * tanhf(c);
        g_c_enc[cidx] = c;
        if (s == LSEQ - 1) g_h_enc[cidx] = h;
        __nv_bfloat16 hb = __float2bfloat16(h);
        hsdst[((size_t)t * NB + nb) * HID + u] = hb;
        g_cat[((size_t)dir * NB + nb) * KCAT + XDIM + u] = hb;
    }

    if (blockIdx.x == 0) {
        int tn = dir ? (LSEQ - 2 - s) : (s + 1);
        if (tn >= 0 && tn < LSEQ) {
            for (int e = tid; e < 128 * 64; e += 256) {
                int r = e >> 6, cc = e & 63;
                int nb = brow + r;
                ((uint2*)(g_cat + ((size_t)dir * NB + nb) * KCAT))[cc] =
                ((const uint2*)(g_x + ((size_t)tn * NB + nb) * XDIM))[cc];
            }
        }
    }
}

// ---------------- setup kernels ----------------
__global__ void k_embed(const int* __restrict__ exs, const int* __restrict__ cls,
                        const float* __restrict__ E) {
    int idx = blockIdx.x * blockDim.x + threadIdx.x;
    int j  = idx & (XDIM - 1);
    int tn = idx >> 8;
    int tok = (j < IO_EMB) ? exs[tn] : cls[tn];
    int jj  = (j < IO_EMB) ? j : j - IO_EMB;
    g_x[idx] = __float2bfloat16(E[tok * IO_EMB + jj]);
}

__global__ void k_wcat(const float* __restrict__ Wi_f, const float* __restrict__ Wh_f,
                       const float* __restrict__ Wi_b, const float* __restrict__ Wh_b) {
    int idx = blockIdx.x * blockDim.x + threadIdx.x;
    int dir = idx / (KCAT * GATE);
    int r   = idx - dir * (KCAT * GATE);
    int k   = r / GATE;
    int n   = r - k * GATE;
    int u = n >> 2, g = n & 3;
    int col_orig = g * 512 + u;
    const float* src;
    int kk;
    if (k < XDIM) { src = dir ? Wi_b : Wi_f; kk = k; }
    else          { src = dir ? Wh_b : Wh_f; kk = k - XDIM; }
    g_Wcat[idx] = __float2bfloat16(src[kk * GATE + col_orig]);
}

__global__ void k_conv(const float* __restrict__ W_attn, const float* __restrict__ v_Wi,
                       const float* __restrict__ v_Wh, const float* __restrict__ field,
                       const float* __restrict__ W_comp) {
    int idx = blockIdx.x * blockDim.x + threadIdx.x;   // EH*VG threads
    if (idx < EH * VG) {
        int k = idx >> 12, n = idx & 4095;
        int u = n >> 2, g = n & 3;
        g_vWi_bf[idx] = __float2bfloat16(v_Wi[k * VG + g * 1024 + u]);
        g_vWh_bf[idx] = __float2bfloat16(v_Wh[k * VG + g * 1024 + u]);
    }
    if (idx < EH * EH)      g_Wattn_bf[idx] = __float2bfloat16(W_attn[idx]);
    if (idx < TDEC * EH)    g_field_bf[idx] = __float2bfloat16(field[idx]);
    if (idx < 2048 * NPROD) g_Wcls_bf[idx]  = __float2bfloat16(W_comp[idx]);
}

__global__ void k_init() {
    int idx = blockIdx.x * blockDim.x + threadIdx.x;
    int dir = idx / (NB * KCAT);
    int r   = idx - dir * (NB * KCAT);
    int nb  = r / KCAT;
    int col = r - nb * KCAT;
    if (col < XDIM) {
        int t0 = dir ? (LSEQ - 1) : 0;
        g_cat[idx] = g_x[((size_t)t0 * NB + nb) * XDIM + col];
    } else {
        g_cat[idx] = __float2bfloat16(0.f);
    }
    if (idx < 2 * NB * HID) g_c_enc[idx] = 0.f;
}

// ---------------- pool final encoder states -> decoder init ----------------
__global__ void k_pool() {
    int idx = blockIdx.x * blockDim.x + threadIdx.x;   // BATCH*EH
    int b = idx >> 10;
    int e = idx & 1023;
    int base = (e < 512) ? 0 : NB * HID;
    int ee   = (e < 512) ? e : e - 512;
    float hm = -1e30f, cm = -1e30f;
#pragma unroll
    for (int n = 0; n < 4; n++) {
        int off = base + (b * 4 + n) * HID + ee;
        hm = fmaxf(hm, g_h_enc[off]);
        cm = fmaxf(cm, g_c_enc[off]);
    }
    g_c_dec[idx] = cm;
    __nv_bfloat16 hb = __float2bfloat16(hm);
    g_hdec_bf[idx] = hb;                                 // parity 0
    g_feat[(size_t)b * 2048 + e] = hb;                   // h_hist[0]
}

// ---------------- Phase C: all-timestep attention per (b,n) ----------------
// smem: hsS[64][1032] bf16 | qS[32][1024] bf16 | scS[32][72] f32 | awS[32][64] bf16
#define ATTN_SMEM (64*1032*2 + 32*1024*2 + 32*72*4 + 32*64*2)
__global__ void __launch_bounds__(256) k_attn_all() {
    extern __shared__ char sm[];
    __nv_bfloat16* hsS = (__nv_bfloat16*)sm;
    __nv_bfloat16* qS  = (__nv_bfloat16*)(sm + 64 * 1032 * 2);
    float*         scS = (float*)(sm + 64 * 1032 * 2 + 32 * 1024 * 2);
    __nv_bfloat16* awS = (__nv_bfloat16*)(sm + 64 * 1032 * 2 + 32 * 1024 * 2 + 32 * 72 * 4);

    int nb = blockIdx.x;
    int b  = nb >> 2;
    int tid = threadIdx.x, lane = tid & 31, warp = tid >> 5;

    // load hs tile: [l][0..511]=hs_f, [512..1023]=hs_b
    for (int c = tid; c < 64 * 128; c += 256) {
        int l = c >> 7, off = (c & 127) * 8;
        const __nv_bfloat16* src = (off < 512)
            ? g_hs_f + ((size_t)l * NB + nb) * HID + off
            : g_hs_b + ((size_t)l * NB + nb) * HID + (off - 512);
        *(uint4*)&hsS[l * 1032 + off] = *(const uint4*)src;
    }
    // load q (fp32 -> bf16)
    for (int c = tid; c < 32 * 512; c += 256) {
        int t = c >> 9, d2 = (c & 511) * 2;
        float2 f = *(const float2*)&g_q_all[((size_t)t * BATCH + b) * EH + d2];
        *(__nv_bfloat162*)&qS[t * 1024 + d2] = __float22bfloat162_rn(f);
    }
    __syncthreads();

    // scores[32,64] = Q @ hs^T   (8 warps, one 16x16 tile each)
    {
        int mi = warp >> 2, ni = warp & 3;
        wmma::fragment<wmma::accumulator, 16, 16, 16, float> acc;
        wmma::fill_fragment(acc, 0.f);
        for (int k = 0; k < 1024; k += 16) {
            wmma::fragment<wmma::matrix_a, 16, 16, 16, __nv_bfloat16, wmma::row_major> a;
            wmma::fragment<wmma::matrix_b, 16, 16, 16, __nv_bfloat16, wmma::col_major> bm;
            wmma::load_matrix_sync(a, qS + mi * 16 * 1024 + k, 1024);
            wmma::load_matrix_sync(bm, hsS + (ni * 16) * 1032 + k, 1032);
            wmma::mma_sync(acc, a, bm, acc);
        }
        wmma::store_matrix_sync(scS + mi * 16 * 72 + ni * 16, acc, 72, wmma::mem_row_major);
    }
    __syncthreads();

    // softmax over l per t
    for (int t = warp; t < 32; t += 8) {
        float s0 = scS[t * 72 + lane], s1 = scS[t * 72 + 32 + lane];
        float mx = fmaxf(s0, s1);
#pragma unroll
        for (int o = 16; o > 0; o >>= 1) mx = fmaxf(mx, __shfl_xor_sync(0xffffffffu, mx, o));
        float e0 = __expf(s0 - mx), e1 = __expf(s1 - mx);
        float sum = e0 + e1;
#pragma unroll
        for (int o = 16; o > 0; o >>= 1) sum += __shfl_xor_sync(0xffffffffu, sum, o);
        float inv = 1.f / sum;
        awS[t * 64 + lane]      = __float2bfloat16(e0 * inv);
        awS[t * 64 + 32 + lane] = __float2bfloat16(e1 * inv);
    }
    __syncthreads();

    // ctx[32,1024] = attn @ hs   (each warp owns 128 dims)
    {
        wmma::fragment<wmma::matrix_a, 16, 16, 16, __nv_bfloat16, wmma::row_major> a[2][4];
#pragma unroll
        for (int mi = 0; mi < 2; mi++)
#pragma unroll
            for (int kt = 0; kt < 4; kt++)
                wmma::load_matrix_sync(a[mi][kt], awS + mi * 16 * 64 + kt * 16, 64);
        for (int nt = 0; nt < 8; nt++) {
            int n0 = warp * 128 + nt * 16;
            wmma::fragment<wmma::accumulator, 16, 16, 16, float> acc[2];
            wmma::fill_fragment(acc[0], 0.f);
            wmma::fill_fragment(acc[1], 0.f);
#pragma unroll
            for (int kt = 0; kt < 4; kt++) {
                wmma::fragment<wmma::matrix_b, 16, 16, 16, __nv_bfloat16, wmma::row_major> bm;
                wmma::load_matrix_sync(bm, hsS + kt * 16 * 1032 + n0, 1032);
                wmma::mma_sync(acc[0], a[0][kt], bm, acc[0]);
                wmma::mma_sync(acc[1], a[1][kt], bm, acc[1]);
            }
            // ctx_all[t][nb][d], t-row stride = NB*EH
            wmma::store_matrix_sync(
                g_ctx_all + (size_t)nb * EH + n0, acc[0], NB * EH, wmma::mem_row_major);
            wmma::store_matrix_sync(
                g_ctx_all + (size_t)16 * NB * EH + (size_t)nb * EH + n0, acc[1],
                NB * EH, wmma::mem_row_major);
        }
    }
}

// ---------------- Phase D1: ctx max-pool over IO examples -> feat ----------------
__global__ void k_ctxpool() {
    int idx = blockIdx.x * blockDim.x + threadIdx.x;   // 32*256*1024
    int d  = idx & 1023;
    int tb = idx >> 10;          // t*256 + b
    int b  = tb & 255, t = tb >> 8;
    const float* base = g_ctx_all + ((size_t)t * NB + b * 4) * EH + d;
    float m = fmaxf(fmaxf(base[0], base[EH]), fmaxf(base[2 * EH], base[3 * EH]));
    g_feat[(size_t)tb * 2048 + 1024 + d] = __float2bfloat16(m);
}

// ---------------- Phase D3: per-(t,b) NLL ----------------
__global__ void k_nll(const float* __restrict__ b_comp, const int* __restrict__ actions) {
    int tb = blockIdx.x * blockDim.x + threadIdx.x;    // 0..8191
    int t = tb >> 8, b = tb & 255;
    const float* lg = g_logits + (size_t)tb * NPROD;
    float mx = -1e30f;
    for (int j = 0; j < NPROD; j++) mx = fmaxf(mx, lg[j] + b_comp[j]);
    float sum = 0.f;
    for (int j = 0; j < NPROD; j++) sum += __expf(lg[j] + b_comp[j] - mx);
    int a = actions[b * TDEC + t];
    g_nll[tb] = mx + __logf(sum) - (lg[a] + b_comp[a]);
}

// ---------------- Phase D4: ordered reduce over t ----------------
__global__ void k_out(float* __restrict__ out) {
    int b = threadIdx.x;
    float s = 0.f;
    for (int t = 0; t < TDEC; t++) s += g_nll[t * BATCH + b];
    out[b] = s;
}

// ---------------- host orchestration ----------------
extern "C" void kernel_launch(void* const* d_in, const int* in_sizes, int n_in,
                              void* d_out, int out_size) {
    const int*   exs     = (const int*)  d_in[0];
    const int*   cls     = (const int*)  d_in[1];
    const float* E       = (const float*)d_in[2];
    const float* Wi_f    = (const float*)d_in[3];
    const float* Wh_f    = (const float*)d_in[4];
    const float* b_f     = (const float*)d_in[5];
    const float* Wi_b    = (const float*)d_in[6];
    const float* Wh_b    = (const float*)d_in[7];
    const float* b_b     = (const float*)d_in[8];
    const float* W_attn  = (const float*)d_in[9];
    const float* W_comp  = (const float*)d_in[10];
    const float* b_comp  = (const float*)d_in[11];
    const float* v_Wi    = (const float*)d_in[12];
    const float* v_Wh    = (const float*)d_in[13];
    const float* v_b     = (const float*)d_in[14];
    const float* field   = (const float*)d_in[15];
    const int*   actions = (const int*)  d_in[16];
    float* out = (float*)d_out;

    const int DYN = 128 * 132 * 4;
    cudaFuncSetAttribute(gemm_lstm, cudaFuncAttributeMaxDynamicSharedMemorySize, DYN);
    cudaFuncSetAttribute(k_attn_all, cudaFuncAttributeMaxDynamicSharedMemorySize, ATTN_SMEM);

    __nv_bfloat16 *p_field_bf, *p_vWi_bf, *p_feat, *p_Wattn_bf, *p_Wcls_bf;
    float *p_vXWi, *p_q_all, *p_logits;
    cudaGetSymbolAddress((void**)&p_field_bf, g_field_bf);
    cudaGetSymbolAddress((void**)&p_vWi_bf, g_vWi_bf);
    cudaGetSymbolAddress((void**)&p_feat, g_feat);
    cudaGetSymbolAddress((void**)&p_Wattn_bf, g_Wattn_bf);
    cudaGetSymbolAddress((void**)&p_Wcls_bf, g_Wcls_bf);
    cudaGetSymbolAddress((void**)&p_vXWi, g_vXWi);
    cudaGetSymbolAddress((void**)&p_q_all, g_q_all);
    cudaGetSymbolAddress((void**)&p_logits, g_logits);

    // ---- setup ----
    k_embed<<<(LSEQ * NB * XDIM) / 256, 256>>>(exs, cls, E);
    k_wcat<<<(2 * KCAT * GATE) / 256, 256>>>(Wi_f, Wh_f, Wi_b, Wh_b);
    k_conv<<<(EH * VG) / 256, 256>>>(W_attn, v_Wi, v_Wh, field, W_comp);
    k_init<<<(2 * NB * KCAT) / 256, 256>>>();

    // vXWi = field_emb @ v_Wi(interleaved)   [32, 4096]
    gemm_bf16<<<dim3(VG / BN, 1, 1), 256>>>(
        p_field_bf, p_vWi_bf, p_vXWi, TDEC, VG, EH, EH, VG, VG);

    // ---- biLSTM encoder: 64 fused steps ----
    for (int s = 0; s < LSEQ; s++)
        gemm_lstm<<<dim3(GATE / BN, NB / BM, 2), 256, DYN>>>(b_f, b_b, s);

    // ---- decoder init ----
    k_pool<<<(BATCH * EH) / 256, 256>>>();

    // ---- Phase A: v-LSTM recurrence only (h_hist[32] needed -> 31 steps) ----
    for (int t = 0; t < TDEC - 1; t++)
        gemm_vlstm<<<dim3(VG / 64, BATCH / 64), 128>>>(v_b, t);

    // ---- Phase B: q_all = h_hist @ W_attn   [8192, 1024] ----
    gemm_bf16<<<dim3(EH / BN, TB / BM), 256>>>(
        p_feat, p_Wattn_bf, p_q_all, TB, EH, EH, 2048, EH, EH);

    // ---- Phase C: attention for all t, one pass over hs ----
    k_attn_all<<<NB, 256, ATTN_SMEM>>>();

    // ---- Phase D: pool, logits GEMM, NLL, reduce ----
    k_ctxpool<<<(TDEC * BATCH * EH) / 256, 256>>>();
    gemm64<<<dim3(1, TB / 64), 128>>>(p_feat, p_Wcls_bf, p_logits, 2048, 2048, NPROD, NPROD);
    k_nll<<<TB / 256, 256>>>(b_comp, actions);
    k_out<<<1, BATCH>>>(out);
}

// round 7
// speedup vs baseline: 8.1292x; 1.0993x over previous
#include <cuda_runtime.h>
#include <cuda_bf16.h>
#include <mma.h>
#include <cstdint>
#include <cstddef>
using namespace nvcuda;

// ---------------- problem constants ----------------
#define LSEQ   64
#define BATCH  256
#define NIO    4
#define NB     1024      // BATCH*NIO
#define IO_EMB 128
#define XDIM   256       // 2*IO_EMB
#define HID    512       // IO_HID
#define GATE   2048      // 4*HID
#define KCAT   768       // XDIM + HID
#define EH     1024      // ENC_HID
#define VG     4096      // 4*EH
#define TDEC   32
#define NPROD  64
#define TB     (TDEC * BATCH)   // 8192

// ---------------- device scratch (static, no allocs) ----------------
__device__ __nv_bfloat16 g_x[(size_t)LSEQ * NB * XDIM];
__device__ __nv_bfloat16 g_cat[2 * NB * KCAT];
__device__ __nv_bfloat16 g_Wcat[2 * KCAT * GATE];            // interleaved: col = 4*u + gate
__device__ float g_h_enc[2 * NB * HID];
__device__ float g_c_enc[2 * NB * HID];
__device__ __nv_bfloat16 g_hs_f[(size_t)LSEQ * NB * HID];
__device__ __nv_bfloat16 g_hs_b[(size_t)LSEQ * NB * HID];
__device__ float g_c_dec[BATCH * EH];
__device__ __nv_bfloat16 g_hdec_bf[2 * BATCH * EH];          // parity double buffer
__device__ __nv_bfloat16 g_feat[(size_t)TB * 2048];          // [t*256+b][ h(1024) | ctxp(1024) ]
__device__ float g_q_all[(size_t)TB * EH];
__device__ float g_ctx_all[(size_t)TDEC * NB * EH];
__device__ float g_vXWi[TDEC * VG];                          // interleaved gates
__device__ __nv_bfloat16 g_Wattn_bf[EH * EH];
__device__ __nv_bfloat16 g_vWi_bf[EH * VG];                  // interleaved
__device__ __nv_bfloat16 g_vWh_bf[EH * VG];                  // interleaved
__device__ __nv_bfloat16 g_field_bf[TDEC * EH];
__device__ __nv_bfloat16 g_Wcls_bf[2048 * NPROD];
__device__ float g_logits[(size_t)TB * NPROD];
__device__ float g_nll[TB];

__device__ __forceinline__ float sigf(float x) { return 1.f / (1.f + expf(-x)); }

// ---------------- cp.async helpers ----------------
__device__ __forceinline__ void cp16(void* dst, const void* src, bool valid) {
    unsigned int d = (unsigned int)__cvta_generic_to_shared(dst);
    int sz = valid ? 16 : 0;
    asm volatile("cp.async.cg.shared.global [%0], [%1], 16, %2;" :: "r"(d), "l"(src), "r"(sz));
}
__device__ __forceinline__ void cp_commit() { asm volatile("cp.async.commit_group;"); }
__device__ __forceinline__ void cp_wait1()  { asm volatile("cp.async.wait_group 1;"); }
__device__ __forceinline__ void cp_wait0()  { asm volatile("cp.async.wait_group 0;"); }

#define BM 128
#define BN 128
#define BK 32

// ---------------- 128x128 bf16 tensor-core GEMM ----------------
__global__ void __launch_bounds__(256) gemm_bf16(
    const __nv_bfloat16* __restrict__ A, const __nv_bfloat16* __restrict__ B,
    float* __restrict__ C, int M, int N, int K, int lda, int ldb, int ldc)
{
    __shared__ __nv_bfloat16 As[2][BM][40];
    __shared__ __nv_bfloat16 Bs[2][BK][136];

    int tid  = threadIdx.x;
    int warp = tid >> 5;
    int wr = warp >> 1, wc = warp & 1;
    int brow = blockIdx.y * BM, bcol = blockIdx.x * BN;
    int m0 = wr * 32, n0 = wc * 64;

    wmma::fragment<wmma::accumulator, 16, 16, 16, float> acc[2][4];
#pragma unroll
    for (int i = 0; i < 2; i++)
#pragma unroll
        for (int j = 0; j < 4; j++)
            wmma::fill_fragment(acc[i][j], 0.f);

    int nk = K / BK;

    auto load_tile = [&](int buf, int k0) {
#pragma unroll
        for (int i = 0; i < 2; i++) {
            int cid = tid + i * 256;
            int row = cid >> 2;
            int col = (cid & 3) * 8;
            const __nv_bfloat16* src = A + (size_t)(brow + row) * lda + k0 + col;
            bool v = (brow + row) < M;
            cp16(&As[buf][row][col], v ? (const void*)src : (const void*)A, v);
        }
#pragma unroll
        for (int i = 0; i < 2; i++) {
            int cid = tid + i * 256;
            int row = cid >> 4;
            int col = (cid & 15) * 8;
            cp16(&Bs[buf][row][col], B + (size_t)(k0 + row) * ldb + bcol + col, true);
        }
    };

    load_tile(0, 0);
    cp_commit();

    int buf = 0;
    for (int kt = 0; kt < nk; kt++) {
        if (kt + 1 < nk) { load_tile(buf ^ 1, (kt + 1) * BK); cp_commit(); cp_wait1(); }
        else             { cp_wait0(); }
        __syncthreads();
#pragma unroll
        for (int kk = 0; kk < BK; kk += 16) {
            wmma::fragment<wmma::matrix_a, 16, 16, 16, __nv_bfloat16, wmma::row_major> af[2];
            wmma::fragment<wmma::matrix_b, 16, 16, 16, __nv_bfloat16, wmma::row_major> bfr[4];
#pragma unroll
            for (int i = 0; i < 2; i++)
                wmma::load_matrix_sync(af[i], &As[buf][m0 + i * 16][kk], 40);
#pragma unroll
            for (int j = 0; j < 4; j++)
                wmma::load_matrix_sync(bfr[j], &Bs[buf][kk][n0 + j * 16], 136);
#pragma unroll
            for (int i = 0; i < 2; i++)
#pragma unroll
                for (int j = 0; j < 4; j++)
                    wmma::mma_sync(acc[i][j], af[i], bfr[j], acc[i][j]);
        }
        __syncthreads();
        buf ^= 1;
    }

#pragma unroll
    for (int i = 0; i < 2; i++) {
        int gm = brow + m0 + i * 16;
        if (gm >= M) continue;
#pragma unroll
        for (int j = 0; j < 4; j++)
            wmma::store_matrix_sync(&C[(size_t)gm * ldc + bcol + n0 + j * 16],
                                    acc[i][j], ldc, wmma::mem_row_major);
    }
}

// ---------------- 64x64 bf16 GEMM (narrow matrices) ----------------
__global__ void __launch_bounds__(128) gemm64(
    const __nv_bfloat16* __restrict__ A, const __nv_bfloat16* __restrict__ B,
    float* __restrict__ C, int K, int lda, int ldb, int ldc)
{
    __shared__ __nv_bfloat16 As[2][64][40];
    __shared__ __nv_bfloat16 Bs[2][32][72];

    int tid = threadIdx.x, warp = tid >> 5;
    int m0 = (warp & 1) * 32, n0 = (warp >> 1) * 32;
    int brow = blockIdx.y * 64, bcol = blockIdx.x * 64;

    wmma::fragment<wmma::accumulator, 16, 16, 16, float> acc[2][2];
#pragma unroll
    for (int i = 0; i < 2; i++)
#pragma unroll
        for (int j = 0; j < 2; j++)
            wmma::fill_fragment(acc[i][j], 0.f);

    auto load_tile = [&](int buf, int k0) {
#pragma unroll
        for (int i = 0; i < 2; i++) {
            int cid = tid + i * 128;
            int row = cid >> 2, col = (cid & 3) * 8;
            cp16(&As[buf][row][col], A + (size_t)(brow + row) * lda + k0 + col, true);
        }
#pragma unroll
        for (int i = 0; i < 2; i++) {
            int cid = tid + i * 128;
            int row = cid >> 3, col = (cid & 7) * 8;
            cp16(&Bs[buf][row][col], B + (size_t)(k0 + row) * ldb + bcol + col, true);
        }
    };

    int nk = K / 32;
    load_tile(0, 0);
    cp_commit();
    int buf = 0;
    for (int kt = 0; kt < nk; kt++) {
        if (kt + 1 < nk) { load_tile(buf ^ 1, (kt + 1) * 32); cp_commit(); cp_wait1(); }
        else             { cp_wait0(); }
        __syncthreads();
#pragma unroll
        for (int kk = 0; kk < 32; kk += 16) {
            wmma::fragment<wmma::matrix_a, 16, 16, 16, __nv_bfloat16, wmma::row_major> af[2];
            wmma::fragment<wmma::matrix_b, 16, 16, 16, __nv_bfloat16, wmma::row_major> bfr[2];
#pragma unroll
            for (int i = 0; i < 2; i++)
                wmma::load_matrix_sync(af[i], &As[buf][m0 + i * 16][kk], 40);
#pragma unroll
            for (int j = 0; j < 2; j++)
                wmma::load_matrix_sync(bfr[j], &Bs[buf][kk][n0 + j * 16], 72);
#pragma unroll
            for (int i = 0; i < 2; i++)
#pragma unroll
                for (int j = 0; j < 2; j++)
                    wmma::mma_sync(acc[i][j], af[i], bfr[j], acc[i][j]);
        }
        __syncthreads();
        buf ^= 1;
    }
#pragma unroll
    for (int i = 0; i < 2; i++)
#pragma unroll
        for (int j = 0; j < 2; j++)
            wmma::store_matrix_sync(&C[(size_t)(brow + m0 + i * 16) * ldc + bcol + n0 + j * 16],
                                    acc[i][j], ldc, wmma::mem_row_major);
}

// ---------------- Phase A: fused v-LSTM step, one wave (64x128 tiles) ----------------
// grid (VG/128=32, BATCH/64=4) = 128 blocks, 128 threads
__global__ void __launch_bounds__(128) gemm_vlstm(const float* __restrict__ v_b, int t) {
    __shared__ __align__(16) char smu[64 * 132 * 4];   // union: loads | Cs
    __nv_bfloat16 (*As)[64][40]  = reinterpret_cast<__nv_bfloat16(*)[64][40]>(smu);
    __nv_bfloat16 (*Bs)[32][136] = reinterpret_cast<__nv_bfloat16(*)[32][136]>(smu + 10240);
    float* Cs = reinterpret_cast<float*>(smu);          // [64][132]

    int par = t & 1;
    const __nv_bfloat16* A = g_hdec_bf + (size_t)par * BATCH * EH;
    __nv_bfloat16* hout = g_hdec_bf + (size_t)(par ^ 1) * BATCH * EH;

    int tid = threadIdx.x, warp = tid >> 5;
    int m0 = (warp & 1) * 32, n0 = (warp >> 1) * 64;
    int brow = blockIdx.y * 64, bcol = blockIdx.x * 128;

    wmma::fragment<wmma::accumulator, 16, 16, 16, float> acc[2][4];
#pragma unroll
    for (int i = 0; i < 2; i++)
#pragma unroll
        for (int j = 0; j < 4; j++)
            wmma::fill_fragment(acc[i][j], 0.f);

    auto load_tile = [&](int buf, int k0) {
#pragma unroll
        for (int i = 0; i < 2; i++) {
            int cid = tid + i * 128;
            int row = cid >> 2, col = (cid & 3) * 8;
            cp16(&As[buf][row][col], A + (size_t)(brow + row) * EH + k0 + col, true);
        }
#pragma unroll
        for (int i = 0; i < 4; i++) {
            int cid = tid + i * 128;
            int row = cid >> 4, col = (cid & 15) * 8;
            cp16(&Bs[buf][row][col], g_vWh_bf + (size_t)(k0 + row) * VG + bcol + col, true);
        }
    };

    load_tile(0, 0);
    cp_commit();
    int buf = 0;
    for (int kt = 0; kt < EH / 32; kt++) {
        if (kt + 1 < EH / 32) { load_tile(buf ^ 1, (kt + 1) * 32); cp_commit(); cp_wait1(); }
        else                  { cp_wait0(); }
        __syncthreads();
#pragma unroll
        for (int kk = 0; kk < 32; kk += 16) {
            wmma::fragment<wmma::matrix_a, 16, 16, 16, __nv_bfloat16, wmma::row_major> af[2];
#pragma unroll
            for (int i = 0; i < 2; i++)
                wmma::load_matrix_sync(af[i], &As[buf][m0 + i * 16][kk], 40);
#pragma unroll
            for (int j = 0; j < 4; j++) {
                wmma::fragment<wmma::matrix_b, 16, 16, 16, __nv_bfloat16, wmma::row_major> bfr;
                wmma::load_matrix_sync(bfr, &Bs[buf][kk][n0 + j * 16], 136);
#pragma unroll
                for (int i = 0; i < 2; i++)
                    wmma::mma_sync(acc[i][j], af[i], bfr, acc[i][j]);
            }
        }
        __syncthreads();
        buf ^= 1;
    }

#pragma unroll
    for (int i = 0; i < 2; i++)
#pragma unroll
        for (int j = 0; j < 4; j++)
            wmma::store_matrix_sync(&Cs[(m0 + i * 16) * 132 + n0 + j * 16], acc[i][j], 132,
                                    wmma::mem_row_major);
    __syncthreads();

    // pointwise: block owns 64 rows x 32 units
    const float* xg = g_vXWi + (size_t)t * VG;
    for (int task = tid; task < 64 * 32; task += 128) {
        int r = task >> 5, ju = task & 31;
        int b = brow + r;
        int u = (bcol >> 2) + ju;
        float gi = Cs[r * 132 + ju * 4 + 0] + xg[(u << 2) + 0] + v_b[u];
        float gf = Cs[r * 132 + ju * 4 + 1] + xg[(u << 2) + 1] + v_b[EH + u];
        float gg = Cs[r * 132 + ju * 4 + 2] + xg[(u << 2) + 2] + v_b[2 * EH + u];
        float go = Cs[r * 132 + ju * 4 + 3] + xg[(u << 2) + 3] + v_b[3 * EH + u];
        size_t ci = (size_t)b * EH + u;
        float c = g_c_dec[ci];
        c = sigf(gf) * c + sigf(gi) * tanhf(gg);
        float h = sigf(go) * tanhf(c);
        g_c_dec[ci] = c;
        __nv_bfloat16 hb = __float2bfloat16(h);
        hout[ci] = hb;
        g_feat[((size_t)(t + 1) * BATCH + b) * 2048 + u] = hb;
    }
}

// ---------------- fused encoder step: one wave (128x256 tiles, 512 thr) ----------------
// grid (GATE/256=8, NB/128=8, 2) = 128 blocks
#define ENC_DYN (128 * 260 * 4)   // 133120 B (>= load buffers 54272 B)
__global__ void __launch_bounds__(512) gemm_lstm(
    const float* __restrict__ b_f, const float* __restrict__ b_b, int s)
{
    extern __shared__ __align__(16) char dyn[];
    __nv_bfloat16 (*As)[128][40]  = reinterpret_cast<__nv_bfloat16(*)[128][40]>(dyn);
    __nv_bfloat16 (*Bs)[32][264]  = reinterpret_cast<__nv_bfloat16(*)[32][264]>(dyn + 20480);
    float* Cs = reinterpret_cast<float*>(dyn);           // [128][260]

    int dir = blockIdx.z;
    const __nv_bfloat16* A = g_cat + (size_t)dir * NB * KCAT;
    const __nv_bfloat16* B = g_Wcat + (size_t)dir * KCAT * GATE;

    int tid  = threadIdx.x;
    int warp = tid >> 5;
    int wr = warp >> 2, wc = warp & 3;          // 4x4 warp grid
    int brow = blockIdx.y * 128, bcol = blockIdx.x * 256;
    int m0 = wr * 32, n0 = wc * 64;

    wmma::fragment<wmma::accumulator, 16, 16, 16, float> acc[2][4];
#pragma unroll
    for (int i = 0; i < 2; i++)
#pragma unroll
        for (int j = 0; j < 4; j++)
            wmma::fill_fragment(acc[i][j], 0.f);

    auto load_tile = [&](int buf, int k0) {
        {   // A: 128x32 = 512 chunks, 1 per thread
            int row = tid >> 2, col = (tid & 3) * 8;
            cp16(&As[buf][row][col], A + (size_t)(brow + row) * KCAT + k0 + col, true);
        }
#pragma unroll
        for (int i = 0; i < 2; i++) {   // B: 32x256 = 1024 chunks
            int cid = tid + i * 512;
            int row = cid >> 5, col = (cid & 31) * 8;
            cp16(&Bs[buf][row][col], B + (size_t)(k0 + row) * GATE + bcol + col, true);
        }
    };

    const int nk = KCAT / 32;   // 24
    load_tile(0, 0);
    cp_commit();
    int buf = 0;
    for (int kt = 0; kt < nk; kt++) {
        if (kt + 1 < nk) { load_tile(buf ^ 1, (kt + 1) * 32); cp_commit(); cp_wait1(); }
        else             { cp_wait0(); }
        __syncthreads();
#pragma unroll
        for (int kk = 0; kk < 32; kk += 16) {
            wmma::fragment<wmma::matrix_a, 16, 16, 16, __nv_bfloat16, wmma::row_major> af[2];
#pragma unroll
            for (int i = 0; i < 2; i++)
                wmma::load_matrix_sync(af[i], &As[buf][m0 + i * 16][kk], 40);
#pragma unroll
            for (int j = 0; j < 4; j++) {
                wmma::fragment<wmma::matrix_b, 16, 16, 16, __nv_bfloat16, wmma::row_major> bfr;
                wmma::load_matrix_sync(bfr, &Bs[buf][kk][n0 + j * 16], 264);
#pragma unroll
                for (int i = 0; i < 2; i++)
                    wmma::mma_sync(acc[i][j], af[i], bfr, acc[i][j]);
            }
        }
        __syncthreads();
        buf ^= 1;
    }

    // stage gates to smem
#pragma unroll
    for (int i = 0; i < 2; i++)
#pragma unroll
        for (int j = 0; j < 4; j++)
            wmma::store_matrix_sync(&Cs[(m0 + i * 16) * 260 + n0 + j * 16],
                                    acc[i][j], 260, wmma::mem_row_major);
    __syncthreads();

    const float* bias = dir ? b_b : b_f;
    int t = dir ? (LSEQ - 1 - s) : s;
    __nv_bfloat16* hsdst = dir ? g_hs_b : g_hs_f;

    // 128 rows x 64 units per block
    for (int task = tid; task < 128 * 64; task += 512) {
        int r  = task >> 6;
        int jl = task & 63;
        int nb = brow + r;
        int u  = (bcol >> 2) + jl;
        float gi = Cs[r * 260 + jl * 4 + 0] + bias[u];
        float gf = Cs[r * 260 + jl * 4 + 1] + bias[512 + u];
        float gg = Cs[r * 260 + jl * 4 + 2] + bias[1024 + u];
        float go = Cs[r * 260 + jl * 4 + 3] + bias[1536 + u];
        size_t cidx = ((size_t)dir * NB + nb) * HID + u;
        float c = g_c_enc[cidx];
        c = sigf(gf) * c + sigf(gi) * tanhf(gg);
        float h = sigf(go) * tanhf(c);
        g_c_enc[cidx] = c;
        if (s == LSEQ - 1) g_h_enc[cidx] = h;
        __nv_bfloat16 hb = __float2bfloat16(h);
        hsdst[((size_t)t * NB + nb) * HID + u] = hb;
        g_cat[((size_t)dir * NB + nb) * KCAT + XDIM + u] = hb;
    }

    // x-column refresh for next step (bx==0 blocks own their 128 rows)
    if (blockIdx.x == 0) {
        int tn = dir ? (LSEQ - 2 - s) : (s + 1);
        if (tn >= 0 && tn < LSEQ) {
            for (int e = tid; e < 128 * 64; e += 512) {
                int r = e >> 6, cc = e & 63;
                int nb = brow + r;
                ((uint2*)(g_cat + ((size_t)dir * NB + nb) * KCAT))[cc] =
                ((const uint2*)(g_x + ((size_t)tn * NB + nb) * XDIM))[cc];
            }
        }
    }
}

// ---------------- setup kernels ----------------
__global__ void k_embed(const int* __restrict__ exs, const int* __restrict__ cls,
                        const float* __restrict__ E) {
    int idx = blockIdx.x * blockDim.x + threadIdx.x;
    int j  = idx & (XDIM - 1);
    int tn = idx >> 8;
    int tok = (j < IO_EMB) ? exs[tn] : cls[tn];
    int jj  = (j < IO_EMB) ? j : j - IO_EMB;
    g_x[idx] = __float2bfloat16(E[tok * IO_EMB + jj]);
}

__global__ void k_wcat(const float* __restrict__ Wi_f, const float* __restrict__ Wh_f,
                       const float* __restrict__ Wi_b, const float* __restrict__ Wh_b) {
    int idx = blockIdx.x * blockDim.x + threadIdx.x;
    int dir = idx / (KCAT * GATE);
    int r   = idx - dir * (KCAT * GATE);
    int k   = r / GATE;
    int n   = r - k * GATE;
    int u = n >> 2, g = n & 3;
    int col_orig = g * 512 + u;
    const float* src;
    int kk;
    if (k < XDIM) { src = dir ? Wi_b : Wi_f; kk = k; }
    else          { src = dir ? Wh_b : Wh_f; kk = k - XDIM; }
    g_Wcat[idx] = __float2bfloat16(src[kk * GATE + col_orig]);
}

__global__ void k_conv(const float* __restrict__ W_attn, const float* __restrict__ v_Wi,
                       const float* __restrict__ v_Wh, const float* __restrict__ field,
                       const float* __restrict__ W_comp) {
    int idx = blockIdx.x * blockDim.x + threadIdx.x;   // EH*VG threads
    if (idx < EH * VG) {
        int k = idx >> 12, n = idx & 4095;
        int u = n >> 2, g = n & 3;
        g_vWi_bf[idx] = __float2bfloat16(v_Wi[k * VG + g * 1024 + u]);
        g_vWh_bf[idx] = __float2bfloat16(v_Wh[k * VG + g * 1024 + u]);
    }
    if (idx < EH * EH)      g_Wattn_bf[idx] = __float2bfloat16(W_attn[idx]);
    if (idx < TDEC * EH)    g_field_bf[idx] = __float2bfloat16(field[idx]);
    if (idx < 2048 * NPROD) g_Wcls_bf[idx]  = __float2bfloat16(W_comp[idx]);
}

__global__ void k_init() {
    int idx = blockIdx.x * blockDim.x + threadIdx.x;
    int dir = idx / (NB * KCAT);
    int r   = idx - dir * (NB * KCAT);
    int nb  = r / KCAT;
    int col = r - nb * KCAT;
    if (col < XDIM) {
        int t0 = dir ? (LSEQ - 1) : 0;
        g_cat[idx] = g_x[((size_t)t0 * NB + nb) * XDIM + col];
    } else {
        g_cat[idx] = __float2bfloat16(0.f);
    }
    if (idx < 2 * NB * HID) g_c_enc[idx] = 0.f;
}

// ---------------- pool final encoder states -> decoder init ----------------
__global__ void k_pool() {
    int idx = blockIdx.x * blockDim.x + threadIdx.x;   // BATCH*EH
    int b = idx >> 10;
    int e = idx & 1023;
    int base = (e < 512) ? 0 : NB * HID;
    int ee   = (e < 512) ? e : e - 512;
    float hm = -1e30f, cm = -1e30f;
#pragma unroll
    for (int n = 0; n < 4; n++) {
        int off = base + (b * 4 + n) * HID + ee;
        hm = fmaxf(hm, g_h_enc[off]);
        cm = fmaxf(cm, g_c_enc[off]);
    }
    g_c_dec[idx] = cm;
    __nv_bfloat16 hb = __float2bfloat16(hm);
    g_hdec_bf[idx] = hb;
    g_feat[(size_t)b * 2048 + e] = hb;
}

// ---------------- Phase C: all-timestep attention per (b,n) ----------------
#define ATTN_SMEM (64*1032*2 + 32*1024*2 + 32*72*4 + 32*64*2)
__global__ void __launch_bounds__(256) k_attn_all() {
    extern __shared__ char sm[];
    __nv_bfloat16* hsS = (__nv_bfloat16*)sm;
    __nv_bfloat16* qS  = (__nv_bfloat16*)(sm + 64 * 1032 * 2);
    float*         scS = (float*)(sm + 64 * 1032 * 2 + 32 * 1024 * 2);
    __nv_bfloat16* awS = (__nv_bfloat16*)(sm + 64 * 1032 * 2 + 32 * 1024 * 2 + 32 * 72 * 4);

    int nb = blockIdx.x;
    int b  = nb >> 2;
    int tid = threadIdx.x, lane = tid & 31, warp = tid >> 5;

    for (int c = tid; c < 64 * 128; c += 256) {
        int l = c >> 7, off = (c & 127) * 8;
        const __nv_bfloat16* src = (off < 512)
            ? g_hs_f + ((size_t)l * NB + nb) * HID + off
            : g_hs_b + ((size_t)l * NB + nb) * HID + (off - 512);
        *(uint4*)&hsS[l * 1032 + off] = *(const uint4*)src;
    }
    for (int c = tid; c < 32 * 512; c += 256) {
        int t = c >> 9, d2 = (c & 511) * 2;
        float2 f = *(const float2*)&g_q_all[((size_t)t * BATCH + b) * EH + d2];
        *(__nv_bfloat162*)&qS[t * 1024 + d2] = __float22bfloat162_rn(f);
    }
    __syncthreads();

    {
        int mi = warp >> 2, ni = warp & 3;
        wmma::fragment<wmma::accumulator, 16, 16, 16, float> acc;
        wmma::fill_fragment(acc, 0.f);
        for (int k = 0; k < 1024; k += 16) {
            wmma::fragment<wmma::matrix_a, 16, 16, 16, __nv_bfloat16, wmma::row_major> a;
            wmma::fragment<wmma::matrix_b, 16, 16, 16, __nv_bfloat16, wmma::col_major> bm;
            wmma::load_matrix_sync(a, qS + mi * 16 * 1024 + k, 1024);
            wmma::load_matrix_sync(bm, hsS + (ni * 16) * 1032 + k, 1032);
            wmma::mma_sync(acc, a, bm, acc);
        }
        wmma::store_matrix_sync(scS + mi * 16 * 72 + ni * 16, acc, 72, wmma::mem_row_major);
    }
    __syncthreads();

    for (int t = warp; t < 32; t += 8) {
        float s0 = scS[t * 72 + lane], s1 = scS[t * 72 + 32 + lane];
        float mx = fmaxf(s0, s1);
#pragma unroll
        for (int o = 16; o > 0; o >>= 1) mx = fmaxf(mx, __shfl_xor_sync(0xffffffffu, mx, o));
        float e0 = __expf(s0 - mx), e1 = __expf(s1 - mx);
        float sum = e0 + e1;
#pragma unroll
        for (int o = 16; o > 0; o >>= 1) sum += __shfl_xor_sync(0xffffffffu, sum, o);
        float inv = 1.f / sum;
        awS[t * 64 + lane]      = __float2bfloat16(e0 * inv);
        awS[t * 64 + 32 + lane] = __float2bfloat16(e1 * inv);
    }
    __syncthreads();

    {
        wmma::fragment<wmma::matrix_a, 16, 16, 16, __nv_bfloat16, wmma::row_major> a[2][4];
#pragma unroll
        for (int mi = 0; mi < 2; mi++)
#pragma unroll
            for (int kt = 0; kt < 4; kt++)
                wmma::load_matrix_sync(a[mi][kt], awS + mi * 16 * 64 + kt * 16, 64);
        for (int nt = 0; nt < 8; nt++) {
            int n0 = warp * 128 + nt * 16;
            wmma::fragment<wmma::accumulator, 16, 16, 16, float> acc[2];
            wmma::fill_fragment(acc[0], 0.f);
            wmma::fill_fragment(acc[1], 0.f);
#pragma unroll
            for (int kt = 0; kt < 4; kt++) {
                wmma::fragment<wmma::matrix_b, 16, 16, 16, __nv_bfloat16, wmma::row_major> bm;
                wmma::load_matrix_sync(bm, hsS + kt * 16 * 1032 + n0, 1032);
                wmma::mma_sync(acc[0], a[0][kt], bm, acc[0]);
                wmma::mma_sync(acc[1], a[1][kt], bm, acc[1]);
            }
            wmma::store_matrix_sync(
                g_ctx_all + (size_t)nb * EH + n0, acc[0], NB * EH, wmma::mem_row_major);
            wmma::store_matrix_sync(
                g_ctx_all + (size_t)16 * NB * EH + (size_t)nb * EH + n0, acc[1],
                NB * EH, wmma::mem_row_major);
        }
    }
}

// ---------------- Phase D ----------------
__global__ void k_ctxpool() {
    int idx = blockIdx.x * blockDim.x + threadIdx.x;
    int d  = idx & 1023;
    int tb = idx >> 10;
    int b  = tb & 255, t = tb >> 8;
    const float* base = g_ctx_all + ((size_t)t * NB + b * 4) * EH + d;
    float m = fmaxf(fmaxf(base[0], base[EH]), fmaxf(base[2 * EH], base[3 * EH]));
    g_feat[(size_t)tb * 2048 + 1024 + d] = __float2bfloat16(m);
}

__global__ void k_nll(const float* __restrict__ b_comp, const int* __restrict__ actions) {
    int tb = blockIdx.x * blockDim.x + threadIdx.x;
    int t = tb >> 8, b = tb & 255;
    const float* lg = g_logits + (size_t)tb * NPROD;
    float mx = -1e30f;
    for (int j = 0; j < NPROD; j++) mx = fmaxf(mx, lg[j] + b_comp[j]);
    float sum = 0.f;
    for (int j = 0; j < NPROD; j++) sum += __expf(lg[j] + b_comp[j] - mx);
    int a = actions[b * TDEC + t];
    g_nll[tb] = mx + __logf(sum) - (lg[a] + b_comp[a]);
}

__global__ void k_out(float* __restrict__ out) {
    int b = threadIdx.x;
    float s = 0.f;
    for (int t = 0; t < TDEC; t++) s += g_nll[t * BATCH + b];
    out[b] = s;
}

// ---------------- host orchestration ----------------
extern "C" void kernel_launch(void* const* d_in, const int* in_sizes, int n_in,
                              void* d_out, int out_size) {
    const int*   exs     = (const int*)  d_in[0];
    const int*   cls     = (const int*)  d_in[1];
    const float* E       = (const float*)d_in[2];
    const float* Wi_f    = (const float*)d_in[3];
    const float* Wh_f    = (const float*)d_in[4];
    const float* b_f     = (const float*)d_in[5];
    const float* Wi_b    = (const float*)d_in[6];
    const float* Wh_b    = (const float*)d_in[7];
    const float* b_b     = (const float*)d_in[8];
    const float* W_attn  = (const float*)d_in[9];
    const float* W_comp  = (const float*)d_in[10];
    const float* b_comp  = (const float*)d_in[11];
    const float* v_Wi    = (const float*)d_in[12];
    const float* v_Wh    = (const float*)d_in[13];
    const float* v_b     = (const float*)d_in[14];
    const float* field   = (const float*)d_in[15];
    const int*   actions = (const int*)  d_in[16];
    float* out = (float*)d_out;

    cudaFuncSetAttribute(gemm_lstm, cudaFuncAttributeMaxDynamicSharedMemorySize, ENC_DYN);
    cudaFuncSetAttribute(k_attn_all, cudaFuncAttributeMaxDynamicSharedMemorySize, ATTN_SMEM);

    __nv_bfloat16 *p_field_bf, *p_vWi_bf, *p_feat, *p_Wattn_bf, *p_Wcls_bf;
    float *p_vXWi, *p_q_all, *p_logits;
    cudaGetSymbolAddress((void**)&p_field_bf, g_field_bf);
    cudaGetSymbolAddress((void**)&p_vWi_bf, g_vWi_bf);
    cudaGetSymbolAddress((void**)&p_feat, g_feat);
    cudaGetSymbolAddress((void**)&p_Wattn_bf, g_Wattn_bf);
    cudaGetSymbolAddress((void**)&p_Wcls_bf, g_Wcls_bf);
    cudaGetSymbolAddress((void**)&p_vXWi, g_vXWi);
    cudaGetSymbolAddress((void**)&p_q_all, g_q_all);
    cudaGetSymbolAddress((void**)&p_logits, g_logits);

    // ---- setup ----
    k_embed<<<(LSEQ * NB * XDIM) / 256, 256>>>(exs, cls, E);
    k_wcat<<<(2 * KCAT * GATE) / 256, 256>>>(Wi_f, Wh_f, Wi_b, Wh_b);
    k_conv<<<(EH * VG) / 256, 256>>>(W_attn, v_Wi, v_Wh, field, W_comp);
    k_init<<<(2 * NB * KCAT) / 256, 256>>>();

    // vXWi = field_emb @ v_Wi(interleaved)   [32, 4096]
    gemm_bf16<<<dim3(VG / BN, 1, 1), 256>>>(
        p_field_bf, p_vWi_bf, p_vXWi, TDEC, VG, EH, EH, VG, VG);

    // ---- biLSTM encoder: 64 fused steps, one wave each ----
    for (int s = 0; s < LSEQ; s++)
        gemm_lstm<<<dim3(GATE / 256, NB / 128, 2), 512, ENC_DYN>>>(b_f, b_b, s);

    // ---- decoder init ----
    k_pool<<<(BATCH * EH) / 256, 256>>>();

    // ---- Phase A: v-LSTM recurrence, one wave each ----
    for (int t = 0; t < TDEC - 1; t++)
        gemm_vlstm<<<dim3(VG / 128, BATCH / 64), 128>>>(v_b, t);

    // ---- Phase B: q_all = h_hist @ W_attn ----
    gemm_bf16<<<dim3(EH / BN, TB / BM), 256>>>(
        p_feat, p_Wattn_bf, p_q_all, TB, EH, EH, 2048, EH, EH);

    // ---- Phase C ----
    k_attn_all<<<NB, 256, ATTN_SMEM>>>();

    // ---- Phase D ----
    k_ctxpool<<<(TDEC * BATCH * EH) / 256, 256>>>();
    gemm64<<<dim3(1, TB / 64), 128>>>(p_feat, p_Wcls_bf, p_logits, 2048, 2048, NPROD, NPROD);
    k_nll<<<TB / 256, 256>>>(b_comp, actions);
    k_out<<<1, BATCH>>>(out);
}